// round 10
// baseline (speedup 1.0000x reference)
#include <cuda_runtime.h>
#include <cuda_bf16.h>
#include <math.h>

#define BN 4
#define HH 192
#define WW 192
#define PP (HH*WW)           // 36864
#define CF 64
#define ONC 64
#define INC 7
#define PTILES (PP/128)      // 288

#define NSLICE 4
#define SLICE_P (PP/NSLICE)      // 9216 px (48 rows)
#define SLICE_T (PTILES/NSLICE)  // 72 tiles

#define XSTR 136
#define WSTR 72
#define GEMM_SMEM ((64*XSTR + 64*WSTR) * 4)   // 53248 bytes (dynamic)

typedef unsigned long long u64;

__device__ __forceinline__ void fma2(u64& a, u64 x, u64 w) {
    asm("fma.rn.f32x2 %0, %1, %2, %0;" : "+l"(a) : "l"(x), "l"(w));
}
__device__ __forceinline__ u64 pack2(float s) {
    u64 r; unsigned si = __float_as_uint(s);
    asm("mov.b64 %0, {%1, %2};" : "=l"(r) : "r"(si), "r"(si));
    return r;
}
__device__ __forceinline__ float2 unpack2(u64 v) {
    float2 f; unsigned lo, hi;
    asm("mov.b64 {%0, %1}, %2;" : "=r"(lo), "=r"(hi) : "l"(v));
    f.x = __uint_as_float(lo); f.y = __uint_as_float(hi);
    return f;
}

// ---------------- scratch (device globals; no runtime allocation) ----------------
__device__ float g_dw_s[BN * CF * SLICE_P];     // depthwise slice (L2-resident, reused)
__device__ float g_om_s[BN * 525 * SLICE_P];    // offset/mask slice (L2-resident, reused)
__device__ float g_stack[BN * 3 * ONC * PP];    // stacked branch outputs
__device__ float g_attp[BN * ONC * PTILES];     // attn partial sums
__device__ float g_att[BN * ONC];
__device__ float g_atts[BN * 3 * ONC];
__device__ float g_Wt[65536];                   // transposed weights
__device__ float g_Wbt[BN * 3 * ONC * ONC];     // per-batch folded final weights
__device__ float g_eb[64];                      // branch0 effective bias

#define WT_B0   0
#define WT_B1   4096
#define WT_B2   16384
#define WT_ATT  53248

__device__ __forceinline__ unsigned tf32b(float f) {
    unsigned r; asm("cvt.rna.tf32.f32 %0, %1;" : "=r"(r) : "f"(f)); return r;
}
__device__ __forceinline__ void mma8(float* d, unsigned a0, unsigned a1, unsigned a2, unsigned a3,
                                     unsigned b0, unsigned b1) {
    asm("mma.sync.aligned.m16n8k8.row.col.f32.tf32.tf32.f32 "
        "{%0,%1,%2,%3},{%4,%5,%6,%7},{%8,%9},{%0,%1,%2,%3};"
        : "+f"(d[0]), "+f"(d[1]), "+f"(d[2]), "+f"(d[3])
        : "r"(a0), "r"(a1), "r"(a2), "r"(a3), "r"(b0), "r"(b1));
}

// ---------------- W transpose (+ zero pad) ----------------
__global__ void transposeW_kernel(const float* __restrict__ w, float* __restrict__ wt,
                                  int OC, int OCpad, int C)
{
    int idx = blockIdx.x * blockDim.x + threadIdx.x;
    if (idx >= C * OCpad) return;
    int c = idx / OCpad, oc = idx % OCpad;
    wt[idx] = (oc < OC) ? w[oc * C + c] : 0.f;
}

__global__ void transposeW_scaled_kernel(const float* __restrict__ w,
                                         const float* __restrict__ scale,
                                         const float* __restrict__ dwb,
                                         const float* __restrict__ pwb,
                                         float* __restrict__ wt,
                                         float* __restrict__ eb,
                                         int OC, int OCpad, int C)
{
    int idx = blockIdx.x * blockDim.x + threadIdx.x;
    if (idx < C * OCpad) {
        int c = idx / OCpad, oc = idx % OCpad;
        wt[idx] = (oc < OC) ? w[oc * C + c] * scale[c] : 0.f;
    }
    if (idx < OC) {
        float s = pwb[idx];
        for (int c = 0; c < C; c++) s += w[idx * C + c] * dwb[c];
        eb[idx] = s;
    }
}

// ---------------- depthwise conv slice (k = 3,5), 4 px / thread ----------------
template <int KK>
__global__ void dw_conv_kernel(const float* __restrict__ x,
                               const float* __restrict__ w,
                               const float* __restrict__ bias,
                               float* __restrict__ y,
                               int sliceBase)
{
    const int P4 = SLICE_P / 4;
    int idx = blockIdx.x * blockDim.x + threadIdx.x;
    if (idx >= BN * CF * P4) return;
    int p4 = idx % P4;
    int c  = (idx / P4) % CF;
    int b  = idx / (CF * P4);
    int p  = sliceBase + p4 * 4;           // global pixel
    int h  = p / WW;
    int x0 = p - h * WW;
    const int pad = KK / 2;
    const float* xp = x + ((long)(b * CF + c)) * PP;
    const float* wp = w + c * KK * KK;

    float acc[4];
    float bb = bias[c];
#pragma unroll
    for (int i = 0; i < 4; i++) acc[i] = bb;

    bool inter = (h >= pad) && (h < HH - pad) && (x0 >= pad) && (x0 + 3 + pad < WW);

#pragma unroll
    for (int ky = 0; ky < KK; ky++) {
        int yy = h + ky - pad;
        const float* r = xp + yy * WW + x0 - pad;
        float v[KK + 3];
        if (inter) {
#pragma unroll
            for (int m = 0; m < KK + 3; m++) v[m] = r[m];
        } else {
            bool vy = (yy >= 0) && (yy < HH);
#pragma unroll
            for (int m = 0; m < KK + 3; m++) {
                int xx = x0 - pad + m;
                v[m] = (vy && xx >= 0 && xx < WW) ? xp[yy * WW + xx] : 0.f;
            }
        }
#pragma unroll
        for (int kx = 0; kx < KK; kx++) {
            float wv = wp[ky * KK + kx];
#pragma unroll
            for (int i = 0; i < 4; i++) acc[i] += v[i + kx] * wv;
        }
    }
    *reinterpret_cast<float4*>(y + (long)idx * 4) = make_float4(acc[0], acc[1], acc[2], acc[3]);
}

// ---------------- tf32 pointwise GEMM (Px/Py = channel strides of X/Y) ----------------
__global__ void pw_gemm_tf32_kernel(const float* __restrict__ X,
                                    const float* __restrict__ Wt,
                                    const float* __restrict__ bias,
                                    float* __restrict__ Y,
                                    int C, int OC, int OCpad, int Px, int Py,
                                    long xbs, long ybs, long wbs,
                                    int relu, float* __restrict__ msum, int msumBase)
{
    extern __shared__ float smem[];
    float* Xs = smem;                  // [64][XSTR]
    float* Ws = smem + 64 * XSTR;      // [64][WSTR]
    float* red = Ws;                   // mean-mode partials (aliases Ws)

    int b = blockIdx.z;
    const float* Xb = X + (long)b * xbs;
    const float* Wp = Wt + (long)b * wbs;

    int p0 = blockIdx.x * 128;
    int t = threadIdx.x;
    int lane = t & 31, wid = t >> 5;
    int pw = wid * 16;
    int g = lane >> 2, k4 = lane & 3;

    if (C == 64) {
        for (int i = t; i < 2048; i += 256) {
            int cc = i >> 5, q = i & 31;
            float4 v = reinterpret_cast<const float4*>(Xb + (long)cc * Px + p0)[q];
            float4 o;
            o.x = __uint_as_float(tf32b(v.x)); o.y = __uint_as_float(tf32b(v.y));
            o.z = __uint_as_float(tf32b(v.z)); o.w = __uint_as_float(tf32b(v.w));
            *reinterpret_cast<float4*>(&Xs[cc * XSTR + q * 4]) = o;
        }
        __syncthreads();

        int nT = OCpad >> 6;
        float* Yb = Y + (long)b * ybs;
        for (int ocT = 0; ocT < nT; ocT++) {
            int oc0 = ocT * 64;
            for (int i = t; i < 4096; i += 256) {
                int cc = i >> 6, oo = i & 63;
                Ws[cc * WSTR + oo] = __uint_as_float(tf32b(Wp[(long)cc * OCpad + oc0 + oo]));
            }
            __syncthreads();

            float acc[8][4];
#pragma unroll
            for (int nt = 0; nt < 8; nt++)
#pragma unroll
                for (int j = 0; j < 4; j++) acc[nt][j] = 0.f;

#pragma unroll
            for (int kc = 0; kc < 8; kc++) {
                int kb = kc * 8 + k4;
                unsigned a0 = __float_as_uint(Xs[kb * XSTR + pw + g]);
                unsigned a1 = __float_as_uint(Xs[kb * XSTR + pw + g + 8]);
                unsigned a2 = __float_as_uint(Xs[(kb + 4) * XSTR + pw + g]);
                unsigned a3 = __float_as_uint(Xs[(kb + 4) * XSTR + pw + g + 8]);
#pragma unroll
                for (int nt = 0; nt < 8; nt++) {
                    unsigned b0 = __float_as_uint(Ws[kb * WSTR + nt * 8 + g]);
                    unsigned b1 = __float_as_uint(Ws[(kb + 4) * WSTR + nt * 8 + g]);
                    mma8(acc[nt], a0, a1, a2, a3, b0, b1);
                }
            }

#pragma unroll
            for (int nt = 0; nt < 8; nt++) {
                int oc = oc0 + nt * 8 + k4 * 2;
                int px = p0 + pw + g;
                if (oc < OC) {
                    float bb = bias[oc];
                    float v0 = acc[nt][0] + bb, v2 = acc[nt][2] + bb;
                    if (relu) { v0 = fmaxf(v0, 0.f); v2 = fmaxf(v2, 0.f); }
                    Yb[(long)oc * Py + px]     = v0;
                    Yb[(long)oc * Py + px + 8] = v2;
                }
                if (oc + 1 < OC) {
                    float bb = bias[oc + 1];
                    float v1 = acc[nt][1] + bb, v3 = acc[nt][3] + bb;
                    if (relu) { v1 = fmaxf(v1, 0.f); v3 = fmaxf(v3, 0.f); }
                    Yb[(long)(oc + 1) * Py + px]     = v1;
                    Yb[(long)(oc + 1) * Py + px + 8] = v3;
                }
            }
            __syncthreads();
        }
    } else {
        float acc[8][4];
#pragma unroll
        for (int nt = 0; nt < 8; nt++)
#pragma unroll
            for (int j = 0; j < 4; j++) acc[nt][j] = 0.f;

        for (int c0 = 0; c0 < C; c0 += 64) {
            for (int i = t; i < 2048; i += 256) {
                int cc = i >> 5, q = i & 31;
                float4 v = reinterpret_cast<const float4*>(Xb + (long)(c0 + cc) * Px + p0)[q];
                float4 o;
                o.x = __uint_as_float(tf32b(v.x)); o.y = __uint_as_float(tf32b(v.y));
                o.z = __uint_as_float(tf32b(v.z)); o.w = __uint_as_float(tf32b(v.w));
                *reinterpret_cast<float4*>(&Xs[cc * XSTR + q * 4]) = o;
            }
            for (int i = t; i < 4096; i += 256) {
                int cc = i >> 6, oo = i & 63;
                Ws[cc * WSTR + oo] = __uint_as_float(tf32b(Wp[(long)(c0 + cc) * OCpad + oo]));
            }
            __syncthreads();

#pragma unroll
            for (int kc = 0; kc < 8; kc++) {
                int kb = kc * 8 + k4;
                unsigned a0 = __float_as_uint(Xs[kb * XSTR + pw + g]);
                unsigned a1 = __float_as_uint(Xs[kb * XSTR + pw + g + 8]);
                unsigned a2 = __float_as_uint(Xs[(kb + 4) * XSTR + pw + g]);
                unsigned a3 = __float_as_uint(Xs[(kb + 4) * XSTR + pw + g + 8]);
#pragma unroll
                for (int nt = 0; nt < 8; nt++) {
                    unsigned b0 = __float_as_uint(Ws[kb * WSTR + nt * 8 + g]);
                    unsigned b1 = __float_as_uint(Ws[(kb + 4) * WSTR + nt * 8 + g]);
                    mma8(acc[nt], a0, a1, a2, a3, b0, b1);
                }
            }
            __syncthreads();
        }

        if (msum == nullptr) {
            float* Yb = Y + (long)b * ybs;
#pragma unroll
            for (int nt = 0; nt < 8; nt++) {
                int oc = nt * 8 + k4 * 2;
                int px = p0 + pw + g;
                float b0v = bias[oc], b1v = bias[oc + 1];
                float v0 = acc[nt][0] + b0v, v1 = acc[nt][1] + b1v;
                float v2 = acc[nt][2] + b0v, v3 = acc[nt][3] + b1v;
                if (relu) {
                    v0 = fmaxf(v0, 0.f); v1 = fmaxf(v1, 0.f);
                    v2 = fmaxf(v2, 0.f); v3 = fmaxf(v3, 0.f);
                }
                Yb[(long)oc * Py + px]           = v0;
                Yb[(long)(oc + 1) * Py + px]     = v1;
                Yb[(long)oc * Py + px + 8]       = v2;
                Yb[(long)(oc + 1) * Py + px + 8] = v3;
            }
        } else {
#pragma unroll
            for (int nt = 0; nt < 8; nt++) {
                int oc = nt * 8 + k4 * 2;
                float b0v = bias[oc], b1v = bias[oc + 1];
                float s0 = fmaxf(acc[nt][0] + b0v, 0.f) + fmaxf(acc[nt][2] + b0v, 0.f);
                float s1 = fmaxf(acc[nt][1] + b1v, 0.f) + fmaxf(acc[nt][3] + b1v, 0.f);
#pragma unroll
                for (int off = 4; off < 32; off <<= 1) {
                    s0 += __shfl_xor_sync(0xffffffff, s0, off);
                    s1 += __shfl_xor_sync(0xffffffff, s1, off);
                }
                if (lane < 4) {
                    red[wid * 64 + oc]     = s0;
                    red[wid * 64 + oc + 1] = s1;
                }
            }
            __syncthreads();
            if (t < 64) {
                float s = 0.f;
#pragma unroll
                for (int w = 0; w < 8; w++) s += red[w * 64 + t];
                msum[((long)b * 64 + t) * PTILES + msumBase + blockIdx.x] = s;
            }
        }
    }
}

// ---------------- finish mean ----------------
__global__ void mean_finish_kernel(const float* __restrict__ msum, float* __restrict__ att)
{
    int o = blockIdx.x, b = blockIdx.y;
    const float* p = msum + ((long)b * 64 + o) * PTILES;
    float s = 0.f;
    for (int i = threadIdx.x; i < PTILES; i += 32) s += p[i];
#pragma unroll
    for (int off = 16; off > 0; off >>= 1) s += __shfl_xor_sync(0xffffffff, s, off);
    if (threadIdx.x == 0) att[b * 64 + o] = s / (float)PP;
}

// ---------------- bilinear sample ----------------
__device__ __forceinline__ float msample(const float* __restrict__ xc, float py, float px)
{
    float fy0 = floorf(py), fx0 = floorf(px);
    float wy = py - fy0, wx = px - fx0;
    int iy0 = (int)fy0, ix0 = (int)fx0;
    int iy1 = iy0 + 1, ix1 = ix0 + 1;
    bool vy0 = (iy0 >= 0) & (iy0 < HH);
    bool vy1 = (iy1 >= 0) & (iy1 < HH);
    bool vx0 = (ix0 >= 0) & (ix0 < WW);
    bool vx1 = (ix1 >= 0) & (ix1 < WW);
    int cy0 = min(max(iy0, 0), HH - 1);
    int cy1 = min(max(iy1, 0), HH - 1);
    int cx0 = min(max(ix0, 0), WW - 1);
    int cx1 = min(max(ix1, 0), WW - 1);
    float v00 = (vy0 & vx0) ? xc[cy0 * WW + cx0] : 0.f;
    float v01 = (vy0 & vx1) ? xc[cy0 * WW + cx1] : 0.f;
    float v10 = (vy1 & vx0) ? xc[cy1 * WW + cx0] : 0.f;
    float v11 = (vy1 & vx1) ? xc[cy1 * WW + cx1] : 0.f;
    return v00 * (1.f - wy) * (1.f - wx) + v01 * (1.f - wy) * wx +
           v10 * wy * (1.f - wx) + v11 * wy * wx;
}

// ---------------- mdcn slice, 2 px / thread, f32x2 accumulate ----------------
template <int KK>
__global__ void mdcn_kernel(const float* __restrict__ xin,
                            const float* __restrict__ om,
                            const float* __restrict__ w,
                            const float* __restrict__ bias,
                            float* __restrict__ out,
                            int branch, int sliceBase)
{
    constexpr int K  = KK * KK;
    constexpr int CK = INC * K;
    __shared__ float Ws[CK][64];

    int tid = threadIdx.x;
    for (int i = tid; i < CK * 64; i += blockDim.x) {
        int ck = i >> 6, o = i & 63;
        Ws[ck][o] = w[o * CK + ck];
    }
    __syncthreads();

    int pl = (blockIdx.x * blockDim.x + tid) * 2;   // local (slice) pixel pair
    int b = blockIdx.y;
    if (pl >= SLICE_P) return;
    int pg = sliceBase + pl;                        // global pixel
    int h  = pg / WW;
    int wx = pg - h * WW;
    const int pad = KK / 2;

    const float* omb = om + (long)b * (3 * CK) * SLICE_P;
    const float* xb  = xin + (long)b * INC * PP;

    u64 acc0[32], acc1[32];
#pragma unroll
    for (int j = 0; j < 32; j++) { acc0[j] = 0ULL; acc1[j] = 0ULL; }

    float by = (float)h - (float)pad;
    float bx = (float)wx - (float)pad;

    for (int c = 0; c < INC; c++) {
        const float* xc = xb + c * PP;
#pragma unroll
        for (int kk = 0; kk < K; kk++) {
            int ck = c * K + kk;
            float2 oy = *reinterpret_cast<const float2*>(omb + (long)(2 * ck) * SLICE_P + pl);
            float2 ox = *reinterpret_cast<const float2*>(omb + (long)(2 * ck + 1) * SLICE_P + pl);
            float2 mr = *reinterpret_cast<const float2*>(omb + (long)(2 * CK + ck) * SLICE_P + pl);
            float m0 = 1.f / (1.f + __expf(-mr.x));
            float m1 = 1.f / (1.f + __expf(-mr.y));

            float ty = (float)(kk / KK) + by;
            float tx = (float)(kk % KK) + bx;

            float s0 = msample(xc, oy.x + ty, ox.x + tx) * m0;
            float s1 = msample(xc, oy.y + ty, ox.y + tx + 1.f) * m1;

            u64 s0p = pack2(s0), s1p = pack2(s1);
            const ulonglong2* wr = reinterpret_cast<const ulonglong2*>(&Ws[ck][0]);
#pragma unroll
            for (int j = 0; j < 16; j++) {
                ulonglong2 w2 = wr[j];
                fma2(acc0[2 * j],     s0p, w2.x);
                fma2(acc0[2 * j + 1], s0p, w2.y);
                fma2(acc1[2 * j],     s1p, w2.x);
                fma2(acc1[2 * j + 1], s1p, w2.y);
            }
        }
    }

    float* ob = out + ((long)(b * 3 + branch) * 64) * PP + pg;
#pragma unroll
    for (int j = 0; j < 32; j++) {
        float2 a0 = unpack2(acc0[j]);
        float2 a1 = unpack2(acc1[j]);
        float b0 = bias[2 * j], b1 = bias[2 * j + 1];
        *reinterpret_cast<float2*>(ob + (long)(2 * j) * PP) =
            make_float2(fmaxf(a0.x + b0, 0.f), fmaxf(a1.x + b0, 0.f));
        *reinterpret_cast<float2*>(ob + (long)(2 * j + 1) * PP) =
            make_float2(fmaxf(a0.y + b1, 0.f), fmaxf(a1.y + b1, 0.f));
    }
}

// ---------------- tiny head ----------------
__global__ void head_kernel(const float* __restrict__ att,
                            const float* __restrict__ fc_w, const float* __restrict__ fc_b,
                            const float* __restrict__ fw0, const float* __restrict__ fb0,
                            const float* __restrict__ fw1, const float* __restrict__ fb1,
                            const float* __restrict__ fw2, const float* __restrict__ fb2,
                            const float* __restrict__ conv_w,
                            float* __restrict__ Wbt, float* __restrict__ atts)
{
    __shared__ float a2[BN][32];
    int t = threadIdx.x;
    if (t < BN * 32) {
        int b = t >> 5, o = t & 31;
        float s = fc_b[o];
        for (int c = 0; c < 64; c++) s += fc_w[o * 64 + c] * att[b * 64 + c];
        a2[b][o] = fmaxf(s, 0.f);
    }
    __syncthreads();
    __shared__ float as[BN][192];
    for (int idx = t; idx < BN * 192; idx += blockDim.x) {
        int b = idx / 192, r = idx % 192;
        int i = r / 64, o = r % 64;
        const float* fw = (i == 0) ? fw0 : ((i == 1) ? fw1 : fw2);
        const float* fb = (i == 0) ? fb0 : ((i == 1) ? fb1 : fb2);
        float s = fb[o];
        for (int c = 0; c < 32; c++) s += fw[o * 32 + c] * a2[b][c];
        as[b][r] = s;
        atts[idx] = s;
    }
    __syncthreads();
    for (int idx = t; idx < BN * 192 * 64; idx += blockDim.x) {
        int b  = idx / (192 * 64);
        int r  = idx % (192 * 64);
        int tc = r / 64;
        int o  = r % 64;
        Wbt[idx] = conv_w[o * 192 + tc] * as[b][tc];
    }
}

// ---------------- launch ----------------
extern "C" void kernel_launch(void* const* d_in, const int* in_sizes, int n_in,
                              void* d_out, int out_size)
{
    (void)in_sizes; (void)n_in; (void)out_size;
    const float* fea    = (const float*)d_in[0];
    const float* inputs = (const float*)d_in[1];
    const float* attn_w = (const float*)d_in[20];
    const float* attn_b = (const float*)d_in[21];
    const float* fc_w   = (const float*)d_in[22];
    const float* fc_b   = (const float*)d_in[23];
    const float* conv_w = (const float*)d_in[30];
    const float* conv_b = (const float*)d_in[31];

    float *dws, *oms, *stack, *attp, *att, *atts, *Wt, *Wbt, *eb;
    cudaGetSymbolAddress((void**)&dws, g_dw_s);
    cudaGetSymbolAddress((void**)&oms, g_om_s);
    cudaGetSymbolAddress((void**)&stack, g_stack);
    cudaGetSymbolAddress((void**)&attp, g_attp);
    cudaGetSymbolAddress((void**)&att, g_att);
    cudaGetSymbolAddress((void**)&atts, g_atts);
    cudaGetSymbolAddress((void**)&Wt, g_Wt);
    cudaGetSymbolAddress((void**)&Wbt, g_Wbt);
    cudaGetSymbolAddress((void**)&eb, g_eb);

    cudaFuncSetAttribute(pw_gemm_tf32_kernel,
                         cudaFuncAttributeMaxDynamicSharedMemorySize, GEMM_SMEM);

    const int wtOff[3]  = {WT_B0, WT_B1, WT_B2};
    const int ocPad[3]  = {64, 192, 576};

    // weight transposes (tiny)
    transposeW_scaled_kernel<<<(64 * 64 + 255) / 256, 256>>>(
        (const float*)d_in[4], (const float*)d_in[2], (const float*)d_in[3],
        (const float*)d_in[5], Wt + WT_B0, eb, 21, 64, 64);
    for (int i = 1; i < 3; i++) {
        const float* pww = (const float*)d_in[4 + 6 * i];
        int k = 2 * i + 1;
        int oc = INC * 3 * k * k;
        int n = 64 * ocPad[i];
        transposeW_kernel<<<(n + 255) / 256, 256>>>(pww, Wt + wtOff[i], oc, ocPad[i], 64);
    }
    transposeW_kernel<<<(192 * 64 + 255) / 256, 256>>>(attn_w, Wt + WT_ATT, 64, 64, 192);

    // sliced pipeline: dw -> gemm -> mdcn per branch, then attn gemm, per pixel slice
    for (int s = 0; s < NSLICE; s++) {
        int sliceBase = s * SLICE_P;

        for (int i = 0; i < 3; i++) {
            const float* dww  = (const float*)d_in[2 + 6 * i];
            const float* dwb  = (const float*)d_in[3 + 6 * i];
            const float* pwb  = (const float*)d_in[5 + 6 * i];
            const float* dcnw = (const float*)d_in[6 + 6 * i];
            const float* dcnb = (const float*)d_in[7 + 6 * i];
            int k  = 2 * i + 1;
            int oc = INC * 3 * k * k;   // 21, 189, 525

            const float* gx; long gxbs; int gPx; const float* gb;
            if (i == 0) {
                gx = fea + sliceBase; gxbs = (long)64 * PP; gPx = PP; gb = eb;
            } else {
                int total4 = BN * CF * SLICE_P / 4;
                int blocks = (total4 + 255) / 256;
                if (i == 1) dw_conv_kernel<3><<<blocks, 256>>>(fea, dww, dwb, dws, sliceBase);
                else        dw_conv_kernel<5><<<blocks, 256>>>(fea, dww, dwb, dws, sliceBase);
                gx = dws; gxbs = (long)64 * SLICE_P; gPx = SLICE_P; gb = pwb;
            }

            dim3 ggrid(SLICE_T, 1, BN);
            pw_gemm_tf32_kernel<<<ggrid, 256, GEMM_SMEM>>>(gx, Wt + wtOff[i], gb, oms,
                                                           64, oc, ocPad[i], gPx, SLICE_P,
                                                           gxbs, (long)oc * SLICE_P, 0,
                                                           0, nullptr, 0);

            dim3 mgrid(SLICE_P / 256, BN);
            if (i == 0) mdcn_kernel<1><<<mgrid, 128>>>(inputs, oms, dcnw, dcnb, stack, i, sliceBase);
            if (i == 1) mdcn_kernel<3><<<mgrid, 128>>>(inputs, oms, dcnw, dcnb, stack, i, sliceBase);
            if (i == 2) mdcn_kernel<5><<<mgrid, 128>>>(inputs, oms, dcnw, dcnb, stack, i, sliceBase);
        }

        // attention gemm for this slice (stack slice is L2-warm); mean partials additive
        dim3 agrid(SLICE_T, 1, BN);
        pw_gemm_tf32_kernel<<<agrid, 256, GEMM_SMEM>>>(stack + sliceBase, Wt + WT_ATT, attn_b, nullptr,
                                                       192, 64, 64, PP, PP,
                                                       (long)192 * PP, 0, 0,
                                                       1, attp, s * SLICE_T);
    }

    dim3 rgrid(64, BN);
    mean_finish_kernel<<<rgrid, 32>>>(attp, att);

    head_kernel<<<1, 256>>>(att, fc_w, fc_b,
                            (const float*)d_in[24], (const float*)d_in[25],
                            (const float*)d_in[26], (const float*)d_in[27],
                            (const float*)d_in[28], (const float*)d_in[29],
                            conv_w, Wbt, atts);

    // final: relu(pw(stack, Wbt)) over full P
    dim3 fgrid(PTILES, 1, BN);
    pw_gemm_tf32_kernel<<<fgrid, 256, GEMM_SMEM>>>(stack, Wbt, conv_b, (float*)d_out,
                                                   192, 64, 64, PP, PP,
                                                   (long)192 * PP, (long)64 * PP, (long)192 * 64,
                                                   1, nullptr, 0);
}

// round 11
// speedup vs baseline: 1.5035x; 1.5035x over previous
#include <cuda_runtime.h>
#include <cuda_fp16.h>
#include <math.h>

#define BN 4
#define HH 192
#define WW 192
#define PP (HH*WW)           // 36864
#define CF 64
#define ONC 64
#define INC 7
#define PTILES (PP/128)      // 288

#define XSTR 136
#define WSTR 72
#define GEMM_SMEM ((64*XSTR + 64*WSTR) * 4)   // 53248 bytes (dynamic)

typedef unsigned long long u64;

__device__ __forceinline__ void fma2(u64& a, u64 x, u64 w) {
    asm("fma.rn.f32x2 %0, %1, %2, %0;" : "+l"(a) : "l"(x), "l"(w));
}
__device__ __forceinline__ u64 pack2(float s) {
    u64 r; unsigned si = __float_as_uint(s);
    asm("mov.b64 %0, {%1, %2};" : "=l"(r) : "r"(si), "r"(si));
    return r;
}
__device__ __forceinline__ float2 unpack2(u64 v) {
    float2 f; unsigned lo, hi;
    asm("mov.b64 {%0, %1}, %2;" : "=r"(lo), "=r"(hi) : "l"(v));
    f.x = __uint_as_float(lo); f.y = __uint_as_float(hi);
    return f;
}

// ---------------- scratch (device globals; no runtime allocation) ----------------
__device__ float  g_dw[BN * CF * PP];            // depthwise output (fp32)
__device__ __half g_om[BN * 525 * PP];           // offset/mask (fp16)
__device__ __half g_stack[BN * 3 * ONC * PP];    // stacked branch outputs (fp16)
__device__ float  g_attp[BN * ONC * PTILES];     // attn partial sums
__device__ float  g_att[BN * ONC];
__device__ float  g_atts[BN * 3 * ONC];
__device__ float  g_Wt[65536];                   // transposed weights
__device__ float  g_Wbt[BN * 3 * ONC * ONC];     // per-batch folded final weights
__device__ float  g_eb[64];                      // branch0 effective bias

#define WT_B0   0
#define WT_B1   4096
#define WT_B2   16384
#define WT_ATT  53248

__device__ __forceinline__ unsigned tf32b(float f) {
    unsigned r; asm("cvt.rna.tf32.f32 %0, %1;" : "=r"(r) : "f"(f)); return r;
}
__device__ __forceinline__ void mma8(float* d, unsigned a0, unsigned a1, unsigned a2, unsigned a3,
                                     unsigned b0, unsigned b1) {
    asm("mma.sync.aligned.m16n8k8.row.col.f32.tf32.tf32.f32 "
        "{%0,%1,%2,%3},{%4,%5,%6,%7},{%8,%9},{%0,%1,%2,%3};"
        : "+f"(d[0]), "+f"(d[1]), "+f"(d[2]), "+f"(d[3])
        : "r"(a0), "r"(a1), "r"(a2), "r"(a3), "r"(b0), "r"(b1));
}

// ---------------- W transpose (+ zero pad) ----------------
__global__ void transposeW_kernel(const float* __restrict__ w, float* __restrict__ wt,
                                  int OC, int OCpad, int C)
{
    int idx = blockIdx.x * blockDim.x + threadIdx.x;
    if (idx >= C * OCpad) return;
    int c = idx / OCpad, oc = idx % OCpad;
    wt[idx] = (oc < OC) ? w[oc * C + c] : 0.f;
}

__global__ void transposeW_scaled_kernel(const float* __restrict__ w,
                                         const float* __restrict__ scale,
                                         const float* __restrict__ dwb,
                                         const float* __restrict__ pwb,
                                         float* __restrict__ wt,
                                         float* __restrict__ eb,
                                         int OC, int OCpad, int C)
{
    int idx = blockIdx.x * blockDim.x + threadIdx.x;
    if (idx < C * OCpad) {
        int c = idx / OCpad, oc = idx % OCpad;
        wt[idx] = (oc < OC) ? w[oc * C + c] * scale[c] : 0.f;
    }
    if (idx < OC) {
        float s = pwb[idx];
        for (int c = 0; c < C; c++) s += w[idx * C + c] * dwb[c];
        eb[idx] = s;
    }
}

// ---------------- depthwise conv (k = 3,5), 4 px / thread ----------------
template <int KK>
__global__ void dw_conv_kernel(const float* __restrict__ x,
                               const float* __restrict__ w,
                               const float* __restrict__ bias,
                               float* __restrict__ y)
{
    const int P4 = PP / 4;
    int idx = blockIdx.x * blockDim.x + threadIdx.x;
    if (idx >= BN * CF * P4) return;
    int p4 = idx % P4;
    int c  = (idx / P4) % CF;
    int b  = idx / (CF * P4);
    int p  = p4 * 4;
    int h  = p / WW;
    int x0 = p - h * WW;
    const int pad = KK / 2;
    const float* xp = x + ((long)(b * CF + c)) * PP;
    const float* wp = w + c * KK * KK;

    float acc[4];
    float bb = bias[c];
#pragma unroll
    for (int i = 0; i < 4; i++) acc[i] = bb;

    bool inter = (h >= pad) && (h < HH - pad) && (x0 >= pad) && (x0 + 3 + pad < WW);

#pragma unroll
    for (int ky = 0; ky < KK; ky++) {
        int yy = h + ky - pad;
        const float* r = xp + yy * WW + x0 - pad;
        float v[KK + 3];
        if (inter) {
#pragma unroll
            for (int m = 0; m < KK + 3; m++) v[m] = r[m];
        } else {
            bool vy = (yy >= 0) && (yy < HH);
#pragma unroll
            for (int m = 0; m < KK + 3; m++) {
                int xx = x0 - pad + m;
                v[m] = (vy && xx >= 0 && xx < WW) ? xp[yy * WW + xx] : 0.f;
            }
        }
#pragma unroll
        for (int kx = 0; kx < KK; kx++) {
            float wv = wp[ky * KK + kx];
#pragma unroll
            for (int i = 0; i < 4; i++) acc[i] += v[i + kx] * wv;
        }
    }
    *reinterpret_cast<float4*>(y + (long)idx * 4) = make_float4(acc[0], acc[1], acc[2], acc[3]);
}

// ---------------- tf32 pointwise GEMM, templated element types ----------------
// XT/YT in {float, __half}. Path A (C==64): X resident, loop oc tiles.
// Path B (OC==64): chunk over C; optional fused relu+mean (msum != nullptr).
template <typename XT, typename YT>
__global__ void pw_gemm_tf32_kernel(const XT* __restrict__ X,
                                    const float* __restrict__ Wt,
                                    const float* __restrict__ bias,
                                    YT* __restrict__ Y,
                                    int C, int OC, int OCpad,
                                    long xbs, long ybs, long wbs,
                                    int relu, float* __restrict__ msum)
{
    extern __shared__ float smem[];
    float* Xs = smem;                  // [64][XSTR]
    float* Ws = smem + 64 * XSTR;      // [64][WSTR]
    float* red = Ws;                   // mean-mode partials (aliases Ws)

    const int P = PP;
    int b = blockIdx.z;
    const XT* Xb = X + (long)b * xbs;
    const float* Wp = Wt + (long)b * wbs;

    int p0 = blockIdx.x * 128;
    int t = threadIdx.x;
    int lane = t & 31, wid = t >> 5;
    int pw = wid * 16;
    int g = lane >> 2, k4 = lane & 3;

    // ---- X tile loader (c0 offset) ----
    auto loadX = [&](int c0) {
        if constexpr (sizeof(XT) == 4) {
            for (int i = t; i < 2048; i += 256) {
                int cc = i >> 5, q = i & 31;
                float4 v = reinterpret_cast<const float4*>(Xb + (long)(c0 + cc) * P + p0)[q];
                float4 o;
                o.x = __uint_as_float(tf32b(v.x)); o.y = __uint_as_float(tf32b(v.y));
                o.z = __uint_as_float(tf32b(v.z)); o.w = __uint_as_float(tf32b(v.w));
                *reinterpret_cast<float4*>(&Xs[cc * XSTR + q * 4]) = o;
            }
        } else {
            for (int i = t; i < 1024; i += 256) {
                int cc = i >> 4, q = i & 15;
                uint4 v = reinterpret_cast<const uint4*>(Xb + (long)(c0 + cc) * P + p0)[q];
                const __half2* hp = reinterpret_cast<const __half2*>(&v);
                float f[8];
#pragma unroll
                for (int j = 0; j < 4; j++) {
                    float2 ff = __half22float2(hp[j]);
                    f[2 * j] = ff.x; f[2 * j + 1] = ff.y;
                }
                float4 o0, o1;
                o0.x = __uint_as_float(tf32b(f[0])); o0.y = __uint_as_float(tf32b(f[1]));
                o0.z = __uint_as_float(tf32b(f[2])); o0.w = __uint_as_float(tf32b(f[3]));
                o1.x = __uint_as_float(tf32b(f[4])); o1.y = __uint_as_float(tf32b(f[5]));
                o1.z = __uint_as_float(tf32b(f[6])); o1.w = __uint_as_float(tf32b(f[7]));
                *reinterpret_cast<float4*>(&Xs[cc * XSTR + q * 8])     = o0;
                *reinterpret_cast<float4*>(&Xs[cc * XSTR + q * 8 + 4]) = o1;
            }
        }
    };

    if (C == 64) {
        loadX(0);
        __syncthreads();

        int nT = OCpad >> 6;
        YT* Yb = Y + (long)b * ybs;
        for (int ocT = 0; ocT < nT; ocT++) {
            int oc0 = ocT * 64;
            for (int i = t; i < 4096; i += 256) {
                int cc = i >> 6, oo = i & 63;
                Ws[cc * WSTR + oo] = __uint_as_float(tf32b(Wp[(long)cc * OCpad + oc0 + oo]));
            }
            __syncthreads();

            float acc[8][4];
#pragma unroll
            for (int nt = 0; nt < 8; nt++)
#pragma unroll
                for (int j = 0; j < 4; j++) acc[nt][j] = 0.f;

#pragma unroll
            for (int kc = 0; kc < 8; kc++) {
                int kb = kc * 8 + k4;
                unsigned a0 = __float_as_uint(Xs[kb * XSTR + pw + g]);
                unsigned a1 = __float_as_uint(Xs[kb * XSTR + pw + g + 8]);
                unsigned a2 = __float_as_uint(Xs[(kb + 4) * XSTR + pw + g]);
                unsigned a3 = __float_as_uint(Xs[(kb + 4) * XSTR + pw + g + 8]);
#pragma unroll
                for (int nt = 0; nt < 8; nt++) {
                    unsigned b0 = __float_as_uint(Ws[kb * WSTR + nt * 8 + g]);
                    unsigned b1 = __float_as_uint(Ws[(kb + 4) * WSTR + nt * 8 + g]);
                    mma8(acc[nt], a0, a1, a2, a3, b0, b1);
                }
            }

#pragma unroll
            for (int nt = 0; nt < 8; nt++) {
                int oc = oc0 + nt * 8 + k4 * 2;
                int px = p0 + pw + g;
                if (oc < OC) {
                    float bb = bias[oc];
                    float v0 = acc[nt][0] + bb, v2 = acc[nt][2] + bb;
                    if (relu) { v0 = fmaxf(v0, 0.f); v2 = fmaxf(v2, 0.f); }
                    Yb[(long)oc * P + px]     = (YT)v0;
                    Yb[(long)oc * P + px + 8] = (YT)v2;
                }
                if (oc + 1 < OC) {
                    float bb = bias[oc + 1];
                    float v1 = acc[nt][1] + bb, v3 = acc[nt][3] + bb;
                    if (relu) { v1 = fmaxf(v1, 0.f); v3 = fmaxf(v3, 0.f); }
                    Yb[(long)(oc + 1) * P + px]     = (YT)v1;
                    Yb[(long)(oc + 1) * P + px + 8] = (YT)v3;
                }
            }
            __syncthreads();
        }
    } else {
        float acc[8][4];
#pragma unroll
        for (int nt = 0; nt < 8; nt++)
#pragma unroll
            for (int j = 0; j < 4; j++) acc[nt][j] = 0.f;

        for (int c0 = 0; c0 < C; c0 += 64) {
            loadX(c0);
            for (int i = t; i < 4096; i += 256) {
                int cc = i >> 6, oo = i & 63;
                Ws[cc * WSTR + oo] = __uint_as_float(tf32b(Wp[(long)(c0 + cc) * OCpad + oo]));
            }
            __syncthreads();

#pragma unroll
            for (int kc = 0; kc < 8; kc++) {
                int kb = kc * 8 + k4;
                unsigned a0 = __float_as_uint(Xs[kb * XSTR + pw + g]);
                unsigned a1 = __float_as_uint(Xs[kb * XSTR + pw + g + 8]);
                unsigned a2 = __float_as_uint(Xs[(kb + 4) * XSTR + pw + g]);
                unsigned a3 = __float_as_uint(Xs[(kb + 4) * XSTR + pw + g + 8]);
#pragma unroll
                for (int nt = 0; nt < 8; nt++) {
                    unsigned b0 = __float_as_uint(Ws[kb * WSTR + nt * 8 + g]);
                    unsigned b1 = __float_as_uint(Ws[(kb + 4) * WSTR + nt * 8 + g]);
                    mma8(acc[nt], a0, a1, a2, a3, b0, b1);
                }
            }
            __syncthreads();
        }

        if (msum == nullptr) {
            YT* Yb = Y + (long)b * ybs;
#pragma unroll
            for (int nt = 0; nt < 8; nt++) {
                int oc = nt * 8 + k4 * 2;
                int px = p0 + pw + g;
                float b0v = bias[oc], b1v = bias[oc + 1];
                float v0 = acc[nt][0] + b0v, v1 = acc[nt][1] + b1v;
                float v2 = acc[nt][2] + b0v, v3 = acc[nt][3] + b1v;
                if (relu) {
                    v0 = fmaxf(v0, 0.f); v1 = fmaxf(v1, 0.f);
                    v2 = fmaxf(v2, 0.f); v3 = fmaxf(v3, 0.f);
                }
                Yb[(long)oc * P + px]           = (YT)v0;
                Yb[(long)(oc + 1) * P + px]     = (YT)v1;
                Yb[(long)oc * P + px + 8]       = (YT)v2;
                Yb[(long)(oc + 1) * P + px + 8] = (YT)v3;
            }
        } else {
#pragma unroll
            for (int nt = 0; nt < 8; nt++) {
                int oc = nt * 8 + k4 * 2;
                float b0v = bias[oc], b1v = bias[oc + 1];
                float s0 = fmaxf(acc[nt][0] + b0v, 0.f) + fmaxf(acc[nt][2] + b0v, 0.f);
                float s1 = fmaxf(acc[nt][1] + b1v, 0.f) + fmaxf(acc[nt][3] + b1v, 0.f);
#pragma unroll
                for (int off = 4; off < 32; off <<= 1) {
                    s0 += __shfl_xor_sync(0xffffffff, s0, off);
                    s1 += __shfl_xor_sync(0xffffffff, s1, off);
                }
                if (lane < 4) {
                    red[wid * 64 + oc]     = s0;
                    red[wid * 64 + oc + 1] = s1;
                }
            }
            __syncthreads();
            if (t < 64) {
                float s = 0.f;
#pragma unroll
                for (int w = 0; w < 8; w++) s += red[w * 64 + t];
                msum[((long)b * 64 + t) * gridDim.x + blockIdx.x] = s;
            }
        }
    }
}

// ---------------- finish mean ----------------
__global__ void mean_finish_kernel(const float* __restrict__ msum, float* __restrict__ att)
{
    int o = blockIdx.x, b = blockIdx.y;
    const float* p = msum + ((long)b * 64 + o) * PTILES;
    float s = 0.f;
    for (int i = threadIdx.x; i < PTILES; i += 32) s += p[i];
#pragma unroll
    for (int off = 16; off > 0; off >>= 1) s += __shfl_xor_sync(0xffffffff, s, off);
    if (threadIdx.x == 0) att[b * 64 + o] = s / (float)PP;
}

// ---------------- bilinear sample ----------------
__device__ __forceinline__ float msample(const float* __restrict__ xc, float py, float px)
{
    float fy0 = floorf(py), fx0 = floorf(px);
    float wy = py - fy0, wx = px - fx0;
    int iy0 = (int)fy0, ix0 = (int)fx0;
    int iy1 = iy0 + 1, ix1 = ix0 + 1;
    bool vy0 = (iy0 >= 0) & (iy0 < HH);
    bool vy1 = (iy1 >= 0) & (iy1 < HH);
    bool vx0 = (ix0 >= 0) & (ix0 < WW);
    bool vx1 = (ix1 >= 0) & (ix1 < WW);
    int cy0 = min(max(iy0, 0), HH - 1);
    int cy1 = min(max(iy1, 0), HH - 1);
    int cx0 = min(max(ix0, 0), WW - 1);
    int cx1 = min(max(ix1, 0), WW - 1);
    float v00 = (vy0 & vx0) ? xc[cy0 * WW + cx0] : 0.f;
    float v01 = (vy0 & vx1) ? xc[cy0 * WW + cx1] : 0.f;
    float v10 = (vy1 & vx0) ? xc[cy1 * WW + cx0] : 0.f;
    float v11 = (vy1 & vx1) ? xc[cy1 * WW + cx1] : 0.f;
    return v00 * (1.f - wy) * (1.f - wx) + v01 * (1.f - wy) * wx +
           v10 * wy * (1.f - wx) + v11 * wy * wx;
}

// ---------------- mdcn, 2 px / thread, f32x2 accumulate; om+out fp16 ----------------
template <int KK>
__global__ void mdcn_kernel(const float* __restrict__ xin,
                            const __half* __restrict__ om,
                            const float* __restrict__ w,
                            const float* __restrict__ bias,
                            __half* __restrict__ out,
                            int branch)
{
    constexpr int K  = KK * KK;
    constexpr int CK = INC * K;
    __shared__ float Ws[CK][64];

    int tid = threadIdx.x;
    for (int i = tid; i < CK * 64; i += blockDim.x) {
        int ck = i >> 6, o = i & 63;
        Ws[ck][o] = w[o * CK + ck];
    }
    __syncthreads();

    int pp = (blockIdx.x * blockDim.x + tid) * 2;
    int b = blockIdx.y;
    if (pp >= PP) return;
    int h  = pp / WW;
    int wx = pp - h * WW;
    const int pad = KK / 2;

    const __half* omb = om + (long)b * (3 * CK) * PP;
    const float* xb  = xin + (long)b * INC * PP;

    u64 acc0[32], acc1[32];
#pragma unroll
    for (int j = 0; j < 32; j++) { acc0[j] = 0ULL; acc1[j] = 0ULL; }

    float by = (float)h - (float)pad;
    float bx = (float)wx - (float)pad;

    for (int c = 0; c < INC; c++) {
        const float* xc = xb + c * PP;
#pragma unroll
        for (int kk = 0; kk < K; kk++) {
            int ck = c * K + kk;
            float2 oy = __half22float2(*reinterpret_cast<const __half2*>(omb + (long)(2 * ck) * PP + pp));
            float2 ox = __half22float2(*reinterpret_cast<const __half2*>(omb + (long)(2 * ck + 1) * PP + pp));
            float2 mr = __half22float2(*reinterpret_cast<const __half2*>(omb + (long)(2 * CK + ck) * PP + pp));
            float m0 = 1.f / (1.f + __expf(-mr.x));
            float m1 = 1.f / (1.f + __expf(-mr.y));

            float ty = (float)(kk / KK) + by;
            float tx = (float)(kk % KK) + bx;

            float s0 = msample(xc, oy.x + ty, ox.x + tx) * m0;
            float s1 = msample(xc, oy.y + ty, ox.y + tx + 1.f) * m1;

            u64 s0p = pack2(s0), s1p = pack2(s1);
            const ulonglong2* wr = reinterpret_cast<const ulonglong2*>(&Ws[ck][0]);
#pragma unroll
            for (int j = 0; j < 16; j++) {
                ulonglong2 w2 = wr[j];
                fma2(acc0[2 * j],     s0p, w2.x);
                fma2(acc0[2 * j + 1], s0p, w2.y);
                fma2(acc1[2 * j],     s1p, w2.x);
                fma2(acc1[2 * j + 1], s1p, w2.y);
            }
        }
    }

    __half* ob = out + ((long)(b * 3 + branch) * 64) * PP + pp;
#pragma unroll
    for (int j = 0; j < 32; j++) {
        float2 a0 = unpack2(acc0[j]);
        float2 a1 = unpack2(acc1[j]);
        float b0 = bias[2 * j], b1 = bias[2 * j + 1];
        __half2 h0 = __floats2half2_rn(fmaxf(a0.x + b0, 0.f), fmaxf(a1.x + b0, 0.f));
        __half2 h1 = __floats2half2_rn(fmaxf(a0.y + b1, 0.f), fmaxf(a1.y + b1, 0.f));
        *reinterpret_cast<__half2*>(ob + (long)(2 * j) * PP)     = h0;
        *reinterpret_cast<__half2*>(ob + (long)(2 * j + 1) * PP) = h1;
    }
}

// ---------------- tiny head ----------------
__global__ void head_kernel(const float* __restrict__ att,
                            const float* __restrict__ fc_w, const float* __restrict__ fc_b,
                            const float* __restrict__ fw0, const float* __restrict__ fb0,
                            const float* __restrict__ fw1, const float* __restrict__ fb1,
                            const float* __restrict__ fw2, const float* __restrict__ fb2,
                            const float* __restrict__ conv_w,
                            float* __restrict__ Wbt, float* __restrict__ atts)
{
    __shared__ float a2[BN][32];
    int t = threadIdx.x;
    if (t < BN * 32) {
        int b = t >> 5, o = t & 31;
        float s = fc_b[o];
        for (int c = 0; c < 64; c++) s += fc_w[o * 64 + c] * att[b * 64 + c];
        a2[b][o] = fmaxf(s, 0.f);
    }
    __syncthreads();
    __shared__ float as[BN][192];
    for (int idx = t; idx < BN * 192; idx += blockDim.x) {
        int b = idx / 192, r = idx % 192;
        int i = r / 64, o = r % 64;
        const float* fw = (i == 0) ? fw0 : ((i == 1) ? fw1 : fw2);
        const float* fb = (i == 0) ? fb0 : ((i == 1) ? fb1 : fb2);
        float s = fb[o];
        for (int c = 0; c < 32; c++) s += fw[o * 32 + c] * a2[b][c];
        as[b][r] = s;
        atts[idx] = s;
    }
    __syncthreads();
    for (int idx = t; idx < BN * 192 * 64; idx += blockDim.x) {
        int b  = idx / (192 * 64);
        int r  = idx % (192 * 64);
        int tc = r / 64;
        int o  = r % 64;
        Wbt[idx] = conv_w[o * 192 + tc] * as[b][tc];
    }
}

// ---------------- launch ----------------
extern "C" void kernel_launch(void* const* d_in, const int* in_sizes, int n_in,
                              void* d_out, int out_size)
{
    (void)in_sizes; (void)n_in; (void)out_size;
    const float* fea    = (const float*)d_in[0];
    const float* inputs = (const float*)d_in[1];
    const float* attn_w = (const float*)d_in[20];
    const float* attn_b = (const float*)d_in[21];
    const float* fc_w   = (const float*)d_in[22];
    const float* fc_b   = (const float*)d_in[23];
    const float* conv_w = (const float*)d_in[30];
    const float* conv_b = (const float*)d_in[31];

    float *dw, *attp, *att, *atts, *Wt, *Wbt, *eb;
    __half *om, *stack;
    cudaGetSymbolAddress((void**)&dw, g_dw);
    cudaGetSymbolAddress((void**)&om, g_om);
    cudaGetSymbolAddress((void**)&stack, g_stack);
    cudaGetSymbolAddress((void**)&attp, g_attp);
    cudaGetSymbolAddress((void**)&att, g_att);
    cudaGetSymbolAddress((void**)&atts, g_atts);
    cudaGetSymbolAddress((void**)&Wt, g_Wt);
    cudaGetSymbolAddress((void**)&Wbt, g_Wbt);
    cudaGetSymbolAddress((void**)&eb, g_eb);

    cudaFuncSetAttribute(pw_gemm_tf32_kernel<float, __half>,
                         cudaFuncAttributeMaxDynamicSharedMemorySize, GEMM_SMEM);
    cudaFuncSetAttribute(pw_gemm_tf32_kernel<__half, float>,
                         cudaFuncAttributeMaxDynamicSharedMemorySize, GEMM_SMEM);

    const int wtOff[3]  = {WT_B0, WT_B1, WT_B2};
    const int ocPad[3]  = {64, 192, 576};

    // weight transposes (tiny)
    transposeW_scaled_kernel<<<(64 * 64 + 255) / 256, 256>>>(
        (const float*)d_in[4], (const float*)d_in[2], (const float*)d_in[3],
        (const float*)d_in[5], Wt + WT_B0, eb, 21, 64, 64);
    for (int i = 1; i < 3; i++) {
        const float* pww = (const float*)d_in[4 + 6 * i];
        int k = 2 * i + 1;
        int oc = INC * 3 * k * k;
        int n = 64 * ocPad[i];
        transposeW_kernel<<<(n + 255) / 256, 256>>>(pww, Wt + wtOff[i], oc, ocPad[i], 64);
    }
    transposeW_kernel<<<(192 * 64 + 255) / 256, 256>>>(attn_w, Wt + WT_ATT, 64, 64, 192);

    for (int i = 0; i < 3; i++) {
        const float* dww  = (const float*)d_in[2 + 6 * i];
        const float* dwb  = (const float*)d_in[3 + 6 * i];
        const float* pwb  = (const float*)d_in[5 + 6 * i];
        const float* dcnw = (const float*)d_in[6 + 6 * i];
        const float* dcnb = (const float*)d_in[7 + 6 * i];
        int k  = 2 * i + 1;
        int oc = INC * 3 * k * k;   // 21, 189, 525

        const float* gx = dw;
        const float* gb = pwb;
        if (i == 0) { gx = fea; gb = eb; }
        else {
            int total4 = BN * CF * PP / 4;
            int blocks = (total4 + 255) / 256;
            if (i == 1) dw_conv_kernel<3><<<blocks, 256>>>(fea, dww, dwb, dw);
            else        dw_conv_kernel<5><<<blocks, 256>>>(fea, dww, dwb, dw);
        }

        dim3 ggrid(PTILES, 1, BN);
        pw_gemm_tf32_kernel<float, __half><<<ggrid, 256, GEMM_SMEM>>>(
            gx, Wt + wtOff[i], gb, om,
            64, oc, ocPad[i],
            (long)64 * PP, (long)oc * PP, 0, 0, nullptr);

        dim3 mgrid(PP / 256, BN);
        if (i == 0) mdcn_kernel<1><<<mgrid, 128>>>(inputs, om, dcnw, dcnb, stack, i);
        if (i == 1) mdcn_kernel<3><<<mgrid, 128>>>(inputs, om, dcnw, dcnb, stack, i);
        if (i == 2) mdcn_kernel<5><<<mgrid, 128>>>(inputs, om, dcnw, dcnb, stack, i);
    }

    // attention: relu(pw(stack, attn_w)) -> mean (fused partial sums)
    dim3 agrid(PTILES, 1, BN);
    pw_gemm_tf32_kernel<__half, float><<<agrid, 256, GEMM_SMEM>>>(
        stack, Wt + WT_ATT, attn_b, nullptr,
        192, 64, 64,
        (long)192 * PP, 0, 0, 1, attp);
    dim3 rgrid(64, BN);
    mean_finish_kernel<<<rgrid, 32>>>(attp, att);

    head_kernel<<<1, 256>>>(att, fc_w, fc_b,
                            (const float*)d_in[24], (const float*)d_in[25],
                            (const float*)d_in[26], (const float*)d_in[27],
                            (const float*)d_in[28], (const float*)d_in[29],
                            conv_w, Wbt, atts);

    // final: relu(pw(stack, Wbt)) with atts folded into per-batch transposed weights
    pw_gemm_tf32_kernel<__half, float><<<agrid, 256, GEMM_SMEM>>>(
        stack, Wbt, conv_b, (float*)d_out,
        192, 64, 64,
        (long)192 * PP, (long)64 * PP, (long)192 * 64, 1, nullptr);
}

// round 12
// speedup vs baseline: 1.8318x; 1.2183x over previous
#include <cuda_runtime.h>
#include <cuda_fp16.h>
#include <math.h>

#define BN 4
#define HH 192
#define WW 192
#define PP (HH*WW)           // 36864
#define CF 64
#define ONC 64
#define INC 7
#define PTILES (PP/128)      // 288

#define XSTR 136
#define WSTR 72
#define GEMM_SMEM ((64*XSTR + 64*WSTR) * 4)   // 53248 bytes (dynamic)

// ---------------- scratch (device globals; no runtime allocation) ----------------
__device__ float  g_dw[BN * CF * PP];            // depthwise output (fp32)
__device__ __half g_om[BN * 525 * PP];           // offset/mask (fp16)
__device__ __half g_stack[BN * 3 * ONC * PP];    // stacked branch outputs (fp16)
__device__ float  g_attp[BN * ONC * PTILES];     // attn partial sums
__device__ float  g_att[BN * ONC];
__device__ float  g_atts[BN * 3 * ONC];
__device__ float  g_Wt[65536];                   // transposed pw/attn weights
__device__ float  g_Wdt[20480];                  // transposed dcn weights (zero-padded chunks)
__device__ float  g_Wbt[BN * 3 * ONC * ONC];     // per-batch folded final weights
__device__ float  g_eb[64];                      // branch0 effective bias

#define WT_B0   0
#define WT_B1   4096
#define WT_B2   16384
#define WT_ATT  53248
#define WD_B0   0
#define WD_B1   4096
#define WD_B2   8192

__device__ __forceinline__ unsigned tf32b(float f) {
    unsigned r; asm("cvt.rna.tf32.f32 %0, %1;" : "=r"(r) : "f"(f)); return r;
}
__device__ __forceinline__ void mma8(float* d, unsigned a0, unsigned a1, unsigned a2, unsigned a3,
                                     unsigned b0, unsigned b1) {
    asm("mma.sync.aligned.m16n8k8.row.col.f32.tf32.tf32.f32 "
        "{%0,%1,%2,%3},{%4,%5,%6,%7},{%8,%9},{%0,%1,%2,%3};"
        : "+f"(d[0]), "+f"(d[1]), "+f"(d[2]), "+f"(d[3])
        : "r"(a0), "r"(a1), "r"(a2), "r"(a3), "r"(b0), "r"(b1));
}

// ---------------- W transpose (+ zero pad oc) ----------------
__global__ void transposeW_kernel(const float* __restrict__ w, float* __restrict__ wt,
                                  int OC, int OCpad, int C)
{
    int idx = blockIdx.x * blockDim.x + threadIdx.x;
    if (idx >= C * OCpad) return;
    int c = idx / OCpad, oc = idx % OCpad;
    wt[idx] = (oc < OC) ? w[oc * C + c] : 0.f;
}

// dcn weight transpose (+ zero pad ck rows): wt[ck*64+o] = w[o*CK+ck]
__global__ void transposeWdcn_kernel(const float* __restrict__ w, float* __restrict__ wt,
                                     int CK, int CKpad)
{
    int idx = blockIdx.x * blockDim.x + threadIdx.x;
    if (idx >= CKpad * 64) return;
    int ck = idx / 64, o = idx % 64;
    wt[idx] = (ck < CK) ? w[o * CK + ck] : 0.f;
}

__global__ void transposeW_scaled_kernel(const float* __restrict__ w,
                                         const float* __restrict__ scale,
                                         const float* __restrict__ dwb,
                                         const float* __restrict__ pwb,
                                         float* __restrict__ wt,
                                         float* __restrict__ eb,
                                         int OC, int OCpad, int C)
{
    int idx = blockIdx.x * blockDim.x + threadIdx.x;
    if (idx < C * OCpad) {
        int c = idx / OCpad, oc = idx % OCpad;
        wt[idx] = (oc < OC) ? w[oc * C + c] * scale[c] : 0.f;
    }
    if (idx < OC) {
        float s = pwb[idx];
        for (int c = 0; c < C; c++) s += w[idx * C + c] * dwb[c];
        eb[idx] = s;
    }
}

// ---------------- depthwise conv (k = 3,5), 4 px / thread ----------------
template <int KK>
__global__ void dw_conv_kernel(const float* __restrict__ x,
                               const float* __restrict__ w,
                               const float* __restrict__ bias,
                               float* __restrict__ y)
{
    const int P4 = PP / 4;
    int idx = blockIdx.x * blockDim.x + threadIdx.x;
    if (idx >= BN * CF * P4) return;
    int p4 = idx % P4;
    int c  = (idx / P4) % CF;
    int b  = idx / (CF * P4);
    int p  = p4 * 4;
    int h  = p / WW;
    int x0 = p - h * WW;
    const int pad = KK / 2;
    const float* xp = x + ((long)(b * CF + c)) * PP;
    const float* wp = w + c * KK * KK;

    float acc[4];
    float bb = bias[c];
#pragma unroll
    for (int i = 0; i < 4; i++) acc[i] = bb;

    bool inter = (h >= pad) && (h < HH - pad) && (x0 >= pad) && (x0 + 3 + pad < WW);

#pragma unroll
    for (int ky = 0; ky < KK; ky++) {
        int yy = h + ky - pad;
        const float* r = xp + yy * WW + x0 - pad;
        float v[KK + 3];
        if (inter) {
#pragma unroll
            for (int m = 0; m < KK + 3; m++) v[m] = r[m];
        } else {
            bool vy = (yy >= 0) && (yy < HH);
#pragma unroll
            for (int m = 0; m < KK + 3; m++) {
                int xx = x0 - pad + m;
                v[m] = (vy && xx >= 0 && xx < WW) ? xp[yy * WW + xx] : 0.f;
            }
        }
#pragma unroll
        for (int kx = 0; kx < KK; kx++) {
            float wv = wp[ky * KK + kx];
#pragma unroll
            for (int i = 0; i < 4; i++) acc[i] += v[i + kx] * wv;
        }
    }
    *reinterpret_cast<float4*>(y + (long)idx * 4) = make_float4(acc[0], acc[1], acc[2], acc[3]);
}

// ---------------- tf32 pointwise GEMM, templated element types ----------------
template <typename XT, typename YT>
__global__ void pw_gemm_tf32_kernel(const XT* __restrict__ X,
                                    const float* __restrict__ Wt,
                                    const float* __restrict__ bias,
                                    YT* __restrict__ Y,
                                    int C, int OC, int OCpad,
                                    long xbs, long ybs, long wbs,
                                    int relu, float* __restrict__ msum)
{
    extern __shared__ float smem[];
    float* Xs = smem;
    float* Ws = smem + 64 * XSTR;
    float* red = Ws;

    const int P = PP;
    int b = blockIdx.z;
    const XT* Xb = X + (long)b * xbs;
    const float* Wp = Wt + (long)b * wbs;

    int p0 = blockIdx.x * 128;
    int t = threadIdx.x;
    int lane = t & 31, wid = t >> 5;
    int pw = wid * 16;
    int g = lane >> 2, k4 = lane & 3;

    auto loadX = [&](int c0) {
        if constexpr (sizeof(XT) == 4) {
            for (int i = t; i < 2048; i += 256) {
                int cc = i >> 5, q = i & 31;
                float4 v = reinterpret_cast<const float4*>(Xb + (long)(c0 + cc) * P + p0)[q];
                float4 o;
                o.x = __uint_as_float(tf32b(v.x)); o.y = __uint_as_float(tf32b(v.y));
                o.z = __uint_as_float(tf32b(v.z)); o.w = __uint_as_float(tf32b(v.w));
                *reinterpret_cast<float4*>(&Xs[cc * XSTR + q * 4]) = o;
            }
        } else {
            for (int i = t; i < 1024; i += 256) {
                int cc = i >> 4, q = i & 15;
                uint4 v = reinterpret_cast<const uint4*>(Xb + (long)(c0 + cc) * P + p0)[q];
                const __half2* hp = reinterpret_cast<const __half2*>(&v);
                float f[8];
#pragma unroll
                for (int j = 0; j < 4; j++) {
                    float2 ff = __half22float2(hp[j]);
                    f[2 * j] = ff.x; f[2 * j + 1] = ff.y;
                }
                float4 o0, o1;
                o0.x = __uint_as_float(tf32b(f[0])); o0.y = __uint_as_float(tf32b(f[1]));
                o0.z = __uint_as_float(tf32b(f[2])); o0.w = __uint_as_float(tf32b(f[3]));
                o1.x = __uint_as_float(tf32b(f[4])); o1.y = __uint_as_float(tf32b(f[5]));
                o1.z = __uint_as_float(tf32b(f[6])); o1.w = __uint_as_float(tf32b(f[7]));
                *reinterpret_cast<float4*>(&Xs[cc * XSTR + q * 8])     = o0;
                *reinterpret_cast<float4*>(&Xs[cc * XSTR + q * 8 + 4]) = o1;
            }
        }
    };

    if (C == 64) {
        loadX(0);
        __syncthreads();

        int nT = OCpad >> 6;
        YT* Yb = Y + (long)b * ybs;
        for (int ocT = 0; ocT < nT; ocT++) {
            int oc0 = ocT * 64;
            for (int i = t; i < 4096; i += 256) {
                int cc = i >> 6, oo = i & 63;
                Ws[cc * WSTR + oo] = __uint_as_float(tf32b(Wp[(long)cc * OCpad + oc0 + oo]));
            }
            __syncthreads();

            float acc[8][4];
#pragma unroll
            for (int nt = 0; nt < 8; nt++)
#pragma unroll
                for (int j = 0; j < 4; j++) acc[nt][j] = 0.f;

#pragma unroll
            for (int kc = 0; kc < 8; kc++) {
                int kb = kc * 8 + k4;
                unsigned a0 = __float_as_uint(Xs[kb * XSTR + pw + g]);
                unsigned a1 = __float_as_uint(Xs[kb * XSTR + pw + g + 8]);
                unsigned a2 = __float_as_uint(Xs[(kb + 4) * XSTR + pw + g]);
                unsigned a3 = __float_as_uint(Xs[(kb + 4) * XSTR + pw + g + 8]);
#pragma unroll
                for (int nt = 0; nt < 8; nt++) {
                    unsigned b0 = __float_as_uint(Ws[kb * WSTR + nt * 8 + g]);
                    unsigned b1 = __float_as_uint(Ws[(kb + 4) * WSTR + nt * 8 + g]);
                    mma8(acc[nt], a0, a1, a2, a3, b0, b1);
                }
            }

#pragma unroll
            for (int nt = 0; nt < 8; nt++) {
                int oc = oc0 + nt * 8 + k4 * 2;
                int px = p0 + pw + g;
                if (oc < OC) {
                    float bb = bias[oc];
                    float v0 = acc[nt][0] + bb, v2 = acc[nt][2] + bb;
                    if (relu) { v0 = fmaxf(v0, 0.f); v2 = fmaxf(v2, 0.f); }
                    Yb[(long)oc * P + px]     = (YT)v0;
                    Yb[(long)oc * P + px + 8] = (YT)v2;
                }
                if (oc + 1 < OC) {
                    float bb = bias[oc + 1];
                    float v1 = acc[nt][1] + bb, v3 = acc[nt][3] + bb;
                    if (relu) { v1 = fmaxf(v1, 0.f); v3 = fmaxf(v3, 0.f); }
                    Yb[(long)(oc + 1) * P + px]     = (YT)v1;
                    Yb[(long)(oc + 1) * P + px + 8] = (YT)v3;
                }
            }
            __syncthreads();
        }
    } else {
        float acc[8][4];
#pragma unroll
        for (int nt = 0; nt < 8; nt++)
#pragma unroll
            for (int j = 0; j < 4; j++) acc[nt][j] = 0.f;

        for (int c0 = 0; c0 < C; c0 += 64) {
            loadX(c0);
            for (int i = t; i < 4096; i += 256) {
                int cc = i >> 6, oo = i & 63;
                Ws[cc * WSTR + oo] = __uint_as_float(tf32b(Wp[(long)(c0 + cc) * OCpad + oo]));
            }
            __syncthreads();

#pragma unroll
            for (int kc = 0; kc < 8; kc++) {
                int kb = kc * 8 + k4;
                unsigned a0 = __float_as_uint(Xs[kb * XSTR + pw + g]);
                unsigned a1 = __float_as_uint(Xs[kb * XSTR + pw + g + 8]);
                unsigned a2 = __float_as_uint(Xs[(kb + 4) * XSTR + pw + g]);
                unsigned a3 = __float_as_uint(Xs[(kb + 4) * XSTR + pw + g + 8]);
#pragma unroll
                for (int nt = 0; nt < 8; nt++) {
                    unsigned b0 = __float_as_uint(Ws[kb * WSTR + nt * 8 + g]);
                    unsigned b1 = __float_as_uint(Ws[(kb + 4) * WSTR + nt * 8 + g]);
                    mma8(acc[nt], a0, a1, a2, a3, b0, b1);
                }
            }
            __syncthreads();
        }

        if (msum == nullptr) {
            YT* Yb = Y + (long)b * ybs;
#pragma unroll
            for (int nt = 0; nt < 8; nt++) {
                int oc = nt * 8 + k4 * 2;
                int px = p0 + pw + g;
                float b0v = bias[oc], b1v = bias[oc + 1];
                float v0 = acc[nt][0] + b0v, v1 = acc[nt][1] + b1v;
                float v2 = acc[nt][2] + b0v, v3 = acc[nt][3] + b1v;
                if (relu) {
                    v0 = fmaxf(v0, 0.f); v1 = fmaxf(v1, 0.f);
                    v2 = fmaxf(v2, 0.f); v3 = fmaxf(v3, 0.f);
                }
                Yb[(long)oc * P + px]           = (YT)v0;
                Yb[(long)(oc + 1) * P + px]     = (YT)v1;
                Yb[(long)oc * P + px + 8]       = (YT)v2;
                Yb[(long)(oc + 1) * P + px + 8] = (YT)v3;
            }
        } else {
#pragma unroll
            for (int nt = 0; nt < 8; nt++) {
                int oc = nt * 8 + k4 * 2;
                float b0v = bias[oc], b1v = bias[oc + 1];
                float s0 = fmaxf(acc[nt][0] + b0v, 0.f) + fmaxf(acc[nt][2] + b0v, 0.f);
                float s1 = fmaxf(acc[nt][1] + b1v, 0.f) + fmaxf(acc[nt][3] + b1v, 0.f);
#pragma unroll
                for (int off = 4; off < 32; off <<= 1) {
                    s0 += __shfl_xor_sync(0xffffffff, s0, off);
                    s1 += __shfl_xor_sync(0xffffffff, s1, off);
                }
                if (lane < 4) {
                    red[wid * 64 + oc]     = s0;
                    red[wid * 64 + oc + 1] = s1;
                }
            }
            __syncthreads();
            if (t < 64) {
                float s = 0.f;
#pragma unroll
                for (int w = 0; w < 8; w++) s += red[w * 64 + t];
                msum[((long)b * 64 + t) * gridDim.x + blockIdx.x] = s;
            }
        }
    }
}

// ---------------- finish mean ----------------
__global__ void mean_finish_kernel(const float* __restrict__ msum, float* __restrict__ att)
{
    int o = blockIdx.x, b = blockIdx.y;
    const float* p = msum + ((long)b * 64 + o) * PTILES;
    float s = 0.f;
    for (int i = threadIdx.x; i < PTILES; i += 32) s += p[i];
#pragma unroll
    for (int off = 16; off > 0; off >>= 1) s += __shfl_xor_sync(0xffffffff, s, off);
    if (threadIdx.x == 0) att[b * 64 + o] = s / (float)PP;
}

// ---------------- bilinear sample ----------------
__device__ __forceinline__ float msample(const float* __restrict__ xc, float py, float px)
{
    float fy0 = floorf(py), fx0 = floorf(px);
    float wy = py - fy0, wx = px - fx0;
    int iy0 = (int)fy0, ix0 = (int)fx0;
    int iy1 = iy0 + 1, ix1 = ix0 + 1;
    bool vy0 = (iy0 >= 0) & (iy0 < HH);
    bool vy1 = (iy1 >= 0) & (iy1 < HH);
    bool vx0 = (ix0 >= 0) & (ix0 < WW);
    bool vx1 = (ix1 >= 0) & (ix1 < WW);
    int cy0 = min(max(iy0, 0), HH - 1);
    int cy1 = min(max(iy1, 0), HH - 1);
    int cx0 = min(max(ix0, 0), WW - 1);
    int cx1 = min(max(ix1, 0), WW - 1);
    float v00 = (vy0 & vx0) ? xc[cy0 * WW + cx0] : 0.f;
    float v01 = (vy0 & vx1) ? xc[cy0 * WW + cx1] : 0.f;
    float v10 = (vy1 & vx0) ? xc[cy1 * WW + cx0] : 0.f;
    float v11 = (vy1 & vx1) ? xc[cy1 * WW + cx1] : 0.f;
    return v00 * (1.f - wy) * (1.f - wx) + v01 * (1.f - wy) * wx +
           v10 * wy * (1.f - wx) + v11 * wy * wx;
}

// ---------------- mdcn as tf32 GEMM with on-the-fly sample generation ----------------
// Block: 256 threads, 128-px tile, all 64 oc. Loop over ck chunks of 64.
template <int KK>
__global__ void mdcn_tf32_kernel(const float* __restrict__ xin,
                                 const __half* __restrict__ om,
                                 const float* __restrict__ Wdt,
                                 const float* __restrict__ bias,
                                 __half* __restrict__ out,
                                 int branch)
{
    constexpr int K  = KK * KK;
    constexpr int CK = INC * K;
    constexpr int CKpad = ((CK + 63) / 64) * 64;
    constexpr int pad = KK / 2;

    extern __shared__ float smem[];
    float* Xs = smem;                  // [64][XSTR] sample tile (tf32)
    float* Ws = smem + 64 * XSTR;      // [64][WSTR]

    int b = blockIdx.z;
    int p0 = blockIdx.x * 128;
    int t = threadIdx.x;
    int lane = t & 31, wid = t >> 5;
    int pw = wid * 16;
    int g = lane >> 2, k4 = lane & 3;

    const __half* omb = om + (long)b * (3 * CK) * PP;
    const float* xb  = xin + (long)b * INC * PP;

    float acc[8][4];
#pragma unroll
    for (int nt = 0; nt < 8; nt++)
#pragma unroll
        for (int j = 0; j < 4; j++) acc[nt][j] = 0.f;

    for (int c0 = 0; c0 < CKpad; c0 += 64) {
        // generate 64 x 128 sample tile (coalesced om reads along px)
        for (int i = t; i < 8192; i += 256) {
            int cc = i >> 7, pxl = i & 127;
            int ck = c0 + cc;
            float val = 0.f;
            if (ck < CK) {
                int p = p0 + pxl;
                int h = p / WW;
                int wxp = p - h * WW;
                float oy = __half2float(omb[(long)(2 * ck) * PP + p]);
                float ox = __half2float(omb[(long)(2 * ck + 1) * PP + p]);
                float mr = __half2float(omb[(long)(2 * CK + ck) * PP + p]);
                float m = 1.f / (1.f + __expf(-mr));
                int c  = ck / K;
                int kk = ck - c * K;
                int ky = kk / KK;
                int kx = kk - ky * KK;
                float py = oy + (float)(ky + h - pad);
                float px = ox + (float)(kx + wxp - pad);
                val = msample(xb + c * PP, py, px) * m;
            }
            Xs[cc * XSTR + pxl] = __uint_as_float(tf32b(val));
        }
        // weights chunk (already transposed + zero padded)
        for (int i = t; i < 4096; i += 256) {
            int cc = i >> 6, oo = i & 63;
            Ws[cc * WSTR + oo] = __uint_as_float(tf32b(Wdt[(long)(c0 + cc) * 64 + oo]));
        }
        __syncthreads();

#pragma unroll
        for (int kc = 0; kc < 8; kc++) {
            int kb = kc * 8 + k4;
            unsigned a0 = __float_as_uint(Xs[kb * XSTR + pw + g]);
            unsigned a1 = __float_as_uint(Xs[kb * XSTR + pw + g + 8]);
            unsigned a2 = __float_as_uint(Xs[(kb + 4) * XSTR + pw + g]);
            unsigned a3 = __float_as_uint(Xs[(kb + 4) * XSTR + pw + g + 8]);
#pragma unroll
            for (int nt = 0; nt < 8; nt++) {
                unsigned b0 = __float_as_uint(Ws[kb * WSTR + nt * 8 + g]);
                unsigned b1 = __float_as_uint(Ws[(kb + 4) * WSTR + nt * 8 + g]);
                mma8(acc[nt], a0, a1, a2, a3, b0, b1);
            }
        }
        __syncthreads();
    }

    __half* ob = out + ((long)(b * 3 + branch) * 64) * PP;
#pragma unroll
    for (int nt = 0; nt < 8; nt++) {
        int oc = nt * 8 + k4 * 2;
        int px = p0 + pw + g;
        float b0v = bias[oc], b1v = bias[oc + 1];
        float v0 = fmaxf(acc[nt][0] + b0v, 0.f);
        float v1 = fmaxf(acc[nt][1] + b1v, 0.f);
        float v2 = fmaxf(acc[nt][2] + b0v, 0.f);
        float v3 = fmaxf(acc[nt][3] + b1v, 0.f);
        ob[(long)oc * PP + px]           = (__half)v0;
        ob[(long)(oc + 1) * PP + px]     = (__half)v1;
        ob[(long)oc * PP + px + 8]       = (__half)v2;
        ob[(long)(oc + 1) * PP + px + 8] = (__half)v3;
    }
}

// ---------------- tiny head ----------------
__global__ void head_kernel(const float* __restrict__ att,
                            const float* __restrict__ fc_w, const float* __restrict__ fc_b,
                            const float* __restrict__ fw0, const float* __restrict__ fb0,
                            const float* __restrict__ fw1, const float* __restrict__ fb1,
                            const float* __restrict__ fw2, const float* __restrict__ fb2,
                            const float* __restrict__ conv_w,
                            float* __restrict__ Wbt, float* __restrict__ atts)
{
    __shared__ float a2[BN][32];
    int t = threadIdx.x;
    if (t < BN * 32) {
        int b = t >> 5, o = t & 31;
        float s = fc_b[o];
        for (int c = 0; c < 64; c++) s += fc_w[o * 64 + c] * att[b * 64 + c];
        a2[b][o] = fmaxf(s, 0.f);
    }
    __syncthreads();
    __shared__ float as[BN][192];
    for (int idx = t; idx < BN * 192; idx += blockDim.x) {
        int b = idx / 192, r = idx % 192;
        int i = r / 64, o = r % 64;
        const float* fw = (i == 0) ? fw0 : ((i == 1) ? fw1 : fw2);
        const float* fb = (i == 0) ? fb0 : ((i == 1) ? fb1 : fb2);
        float s = fb[o];
        for (int c = 0; c < 32; c++) s += fw[o * 32 + c] * a2[b][c];
        as[b][r] = s;
        atts[idx] = s;
    }
    __syncthreads();
    for (int idx = t; idx < BN * 192 * 64; idx += blockDim.x) {
        int b  = idx / (192 * 64);
        int r  = idx % (192 * 64);
        int tc = r / 64;
        int o  = r % 64;
        Wbt[idx] = conv_w[o * 192 + tc] * as[b][tc];
    }
}

// ---------------- launch ----------------
extern "C" void kernel_launch(void* const* d_in, const int* in_sizes, int n_in,
                              void* d_out, int out_size)
{
    (void)in_sizes; (void)n_in; (void)out_size;
    const float* fea    = (const float*)d_in[0];
    const float* inputs = (const float*)d_in[1];
    const float* attn_w = (const float*)d_in[20];
    const float* attn_b = (const float*)d_in[21];
    const float* fc_w   = (const float*)d_in[22];
    const float* fc_b   = (const float*)d_in[23];
    const float* conv_w = (const float*)d_in[30];
    const float* conv_b = (const float*)d_in[31];

    float *dw, *attp, *att, *atts, *Wt, *Wdt, *Wbt, *eb;
    __half *om, *stack;
    cudaGetSymbolAddress((void**)&dw, g_dw);
    cudaGetSymbolAddress((void**)&om, g_om);
    cudaGetSymbolAddress((void**)&stack, g_stack);
    cudaGetSymbolAddress((void**)&attp, g_attp);
    cudaGetSymbolAddress((void**)&att, g_att);
    cudaGetSymbolAddress((void**)&atts, g_atts);
    cudaGetSymbolAddress((void**)&Wt, g_Wt);
    cudaGetSymbolAddress((void**)&Wdt, g_Wdt);
    cudaGetSymbolAddress((void**)&Wbt, g_Wbt);
    cudaGetSymbolAddress((void**)&eb, g_eb);

    cudaFuncSetAttribute(pw_gemm_tf32_kernel<float, __half>,
                         cudaFuncAttributeMaxDynamicSharedMemorySize, GEMM_SMEM);
    cudaFuncSetAttribute(pw_gemm_tf32_kernel<__half, float>,
                         cudaFuncAttributeMaxDynamicSharedMemorySize, GEMM_SMEM);
    cudaFuncSetAttribute(mdcn_tf32_kernel<1>,
                         cudaFuncAttributeMaxDynamicSharedMemorySize, GEMM_SMEM);
    cudaFuncSetAttribute(mdcn_tf32_kernel<3>,
                         cudaFuncAttributeMaxDynamicSharedMemorySize, GEMM_SMEM);
    cudaFuncSetAttribute(mdcn_tf32_kernel<5>,
                         cudaFuncAttributeMaxDynamicSharedMemorySize, GEMM_SMEM);

    const int wtOff[3]  = {WT_B0, WT_B1, WT_B2};
    const int wdOff[3]  = {WD_B0, WD_B1, WD_B2};
    const int ocPad[3]  = {64, 192, 576};
    const int ckPad[3]  = {64, 64, 192};
    const int ckArr[3]  = {7, 63, 175};

    // weight transposes (tiny)
    transposeW_scaled_kernel<<<(64 * 64 + 255) / 256, 256>>>(
        (const float*)d_in[4], (const float*)d_in[2], (const float*)d_in[3],
        (const float*)d_in[5], Wt + WT_B0, eb, 21, 64, 64);
    for (int i = 1; i < 3; i++) {
        const float* pww = (const float*)d_in[4 + 6 * i];
        int k = 2 * i + 1;
        int oc = INC * 3 * k * k;
        int n = 64 * ocPad[i];
        transposeW_kernel<<<(n + 255) / 256, 256>>>(pww, Wt + wtOff[i], oc, ocPad[i], 64);
    }
    transposeW_kernel<<<(192 * 64 + 255) / 256, 256>>>(attn_w, Wt + WT_ATT, 64, 64, 192);
    for (int i = 0; i < 3; i++) {
        const float* dcnw = (const float*)d_in[6 + 6 * i];
        int n = ckPad[i] * 64;
        transposeWdcn_kernel<<<(n + 255) / 256, 256>>>(dcnw, Wdt + wdOff[i], ckArr[i], ckPad[i]);
    }

    for (int i = 0; i < 3; i++) {
        const float* dww  = (const float*)d_in[2 + 6 * i];
        const float* dwb  = (const float*)d_in[3 + 6 * i];
        const float* pwb  = (const float*)d_in[5 + 6 * i];
        const float* dcnb = (const float*)d_in[7 + 6 * i];
        int k  = 2 * i + 1;
        int oc = INC * 3 * k * k;   // 21, 189, 525

        const float* gx = dw;
        const float* gb = pwb;
        if (i == 0) { gx = fea; gb = eb; }
        else {
            int total4 = BN * CF * PP / 4;
            int blocks = (total4 + 255) / 256;
            if (i == 1) dw_conv_kernel<3><<<blocks, 256>>>(fea, dww, dwb, dw);
            else        dw_conv_kernel<5><<<blocks, 256>>>(fea, dww, dwb, dw);
        }

        dim3 ggrid(PTILES, 1, BN);
        pw_gemm_tf32_kernel<float, __half><<<ggrid, 256, GEMM_SMEM>>>(
            gx, Wt + wtOff[i], gb, om,
            64, oc, ocPad[i],
            (long)64 * PP, (long)oc * PP, 0, 0, nullptr);

        dim3 mgrid(PTILES, 1, BN);
        if (i == 0) mdcn_tf32_kernel<1><<<mgrid, 256, GEMM_SMEM>>>(inputs, om, Wdt + wdOff[i], dcnb, stack, i);
        if (i == 1) mdcn_tf32_kernel<3><<<mgrid, 256, GEMM_SMEM>>>(inputs, om, Wdt + wdOff[i], dcnb, stack, i);
        if (i == 2) mdcn_tf32_kernel<5><<<mgrid, 256, GEMM_SMEM>>>(inputs, om, Wdt + wdOff[i], dcnb, stack, i);
    }

    // attention: relu(pw(stack, attn_w)) -> mean (fused partial sums)
    dim3 agrid(PTILES, 1, BN);
    pw_gemm_tf32_kernel<__half, float><<<agrid, 256, GEMM_SMEM>>>(
        stack, Wt + WT_ATT, attn_b, nullptr,
        192, 64, 64,
        (long)192 * PP, 0, 0, 1, attp);
    dim3 rgrid(64, BN);
    mean_finish_kernel<<<rgrid, 32>>>(attp, att);

    head_kernel<<<1, 256>>>(att, fc_w, fc_b,
                            (const float*)d_in[24], (const float*)d_in[25],
                            (const float*)d_in[26], (const float*)d_in[27],
                            (const float*)d_in[28], (const float*)d_in[29],
                            conv_w, Wbt, atts);

    // final: relu(pw(stack, Wbt)) with atts folded into per-batch transposed weights
    pw_gemm_tf32_kernel<__half, float><<<agrid, 256, GEMM_SMEM>>>(
        stack, Wbt, conv_b, (float*)d_out,
        192, 64, 64,
        (long)192 * PP, (long)64 * PP, (long)192 * 64, 1, nullptr);
}

// round 14
// speedup vs baseline: 1.9829x; 1.0825x over previous
#include <cuda_runtime.h>
#include <cuda_fp16.h>
#include <math.h>

#define BN 4
#define HH 192
#define WW 192
#define PP (HH*WW)           // 36864
#define CF 64
#define ONC 64
#define INC 7
#define PTILES (PP/128)      // 288

#define XSTR 136
#define WSTR 72
#define GEMM_SMEM ((64*XSTR + 64*WSTR) * 4)   // 53248 bytes (dynamic)

// ---------------- scratch (device globals; no runtime allocation) ----------------
__device__ float  g_dw[BN * CF * PP];            // depthwise output (fp32)
__device__ __half g_om[BN * 525 * PP];           // offset/mask (fp16)
__device__ __half g_stack[BN * 3 * ONC * PP];    // stacked branch outputs (fp16)
__device__ float  g_attp[BN * ONC * PTILES];     // attn partial sums
__device__ float  g_att[BN * ONC];
__device__ float  g_atts[BN * 3 * ONC];
__device__ float  g_Wt[65536];                   // transposed pw/attn weights
__device__ float  g_Wdt[20480];                  // transposed dcn weights (zero-padded chunks)
__device__ float  g_Wbt[BN * 3 * ONC * ONC];     // per-batch folded final weights
__device__ float  g_eb[64];                      // branch0 effective bias

#define WT_B0   0
#define WT_B1   4096
#define WT_B2   16384
#define WT_ATT  53248
#define WD_B0   0
#define WD_B1   1024
#define WD_B2   5120

__device__ __forceinline__ unsigned tf32b(float f) {
    unsigned r; asm("cvt.rna.tf32.f32 %0, %1;" : "=r"(r) : "f"(f)); return r;
}
__device__ __forceinline__ void mma8(float* d, unsigned a0, unsigned a1, unsigned a2, unsigned a3,
                                     unsigned b0, unsigned b1) {
    asm("mma.sync.aligned.m16n8k8.row.col.f32.tf32.tf32.f32 "
        "{%0,%1,%2,%3},{%4,%5,%6,%7},{%8,%9},{%0,%1,%2,%3};"
        : "+f"(d[0]), "+f"(d[1]), "+f"(d[2]), "+f"(d[3])
        : "r"(a0), "r"(a1), "r"(a2), "r"(a3), "r"(b0), "r"(b1));
}

// ---------------- W transpose (+ zero pad oc) ----------------
__global__ void transposeW_kernel(const float* __restrict__ w, float* __restrict__ wt,
                                  int OC, int OCpad, int C)
{
    int idx = blockIdx.x * blockDim.x + threadIdx.x;
    if (idx >= C * OCpad) return;
    int c = idx / OCpad, oc = idx % OCpad;
    wt[idx] = (oc < OC) ? w[oc * C + c] : 0.f;
}

// dcn weight transpose (+ zero pad ck rows): wt[ck*64+o] = w[o*CK+ck]
__global__ void transposeWdcn_kernel(const float* __restrict__ w, float* __restrict__ wt,
                                     int CK, int CKpad)
{
    int idx = blockIdx.x * blockDim.x + threadIdx.x;
    if (idx >= CKpad * 64) return;
    int ck = idx / 64, o = idx % 64;
    wt[idx] = (ck < CK) ? w[o * CK + ck] : 0.f;
}

__global__ void transposeW_scaled_kernel(const float* __restrict__ w,
                                         const float* __restrict__ scale,
                                         const float* __restrict__ dwb,
                                         const float* __restrict__ pwb,
                                         float* __restrict__ wt,
                                         float* __restrict__ eb,
                                         int OC, int OCpad, int C)
{
    int idx = blockIdx.x * blockDim.x + threadIdx.x;
    if (idx < C * OCpad) {
        int c = idx / OCpad, oc = idx % OCpad;
        wt[idx] = (oc < OC) ? w[oc * C + c] * scale[c] : 0.f;
    }
    if (idx < OC) {
        float s = pwb[idx];
        for (int c = 0; c < C; c++) s += w[idx * C + c] * dwb[c];
        eb[idx] = s;
    }
}

// ---------------- depthwise conv (k = 3,5), 4 px / thread ----------------
template <int KK>
__global__ void dw_conv_kernel(const float* __restrict__ x,
                               const float* __restrict__ w,
                               const float* __restrict__ bias,
                               float* __restrict__ y)
{
    const int P4 = PP / 4;
    int idx = blockIdx.x * blockDim.x + threadIdx.x;
    if (idx >= BN * CF * P4) return;
    int p4 = idx % P4;
    int c  = (idx / P4) % CF;
    int b  = idx / (CF * P4);
    int p  = p4 * 4;
    int h  = p / WW;
    int x0 = p - h * WW;
    const int pad = KK / 2;
    const float* xp = x + ((long)(b * CF + c)) * PP;
    const float* wp = w + c * KK * KK;

    float acc[4];
    float bb = bias[c];
#pragma unroll
    for (int i = 0; i < 4; i++) acc[i] = bb;

    bool inter = (h >= pad) && (h < HH - pad) && (x0 >= pad) && (x0 + 3 + pad < WW);

#pragma unroll
    for (int ky = 0; ky < KK; ky++) {
        int yy = h + ky - pad;
        const float* r = xp + yy * WW + x0 - pad;
        float v[KK + 3];
        if (inter) {
#pragma unroll
            for (int m = 0; m < KK + 3; m++) v[m] = r[m];
        } else {
            bool vy = (yy >= 0) && (yy < HH);
#pragma unroll
            for (int m = 0; m < KK + 3; m++) {
                int xx = x0 - pad + m;
                v[m] = (vy && xx >= 0 && xx < WW) ? xp[yy * WW + xx] : 0.f;
            }
        }
#pragma unroll
        for (int kx = 0; kx < KK; kx++) {
            float wv = wp[ky * KK + kx];
#pragma unroll
            for (int i = 0; i < 4; i++) acc[i] += v[i + kx] * wv;
        }
    }
    *reinterpret_cast<float4*>(y + (long)idx * 4) = make_float4(acc[0], acc[1], acc[2], acc[3]);
}

// ---------------- tf32 pointwise GEMM, templated element types ----------------
template <typename XT, typename YT>
__global__ void pw_gemm_tf32_kernel(const XT* __restrict__ X,
                                    const float* __restrict__ Wt,
                                    const float* __restrict__ bias,
                                    YT* __restrict__ Y,
                                    int C, int OC, int OCpad,
                                    long xbs, long ybs, long wbs,
                                    int relu, float* __restrict__ msum)
{
    extern __shared__ float smem[];
    float* Xs = smem;
    float* Ws = smem + 64 * XSTR;
    float* red = Ws;

    const int P = PP;
    int b = blockIdx.z;
    const XT* Xb = X + (long)b * xbs;
    const float* Wp = Wt + (long)b * wbs;

    int p0 = blockIdx.x * 128;
    int t = threadIdx.x;
    int lane = t & 31, wid = t >> 5;
    int pw = wid * 16;
    int g = lane >> 2, k4 = lane & 3;

    auto loadX = [&](int c0) {
        if constexpr (sizeof(XT) == 4) {
            for (int i = t; i < 2048; i += 256) {
                int cc = i >> 5, q = i & 31;
                float4 v = reinterpret_cast<const float4*>(Xb + (long)(c0 + cc) * P + p0)[q];
                float4 o;
                o.x = __uint_as_float(tf32b(v.x)); o.y = __uint_as_float(tf32b(v.y));
                o.z = __uint_as_float(tf32b(v.z)); o.w = __uint_as_float(tf32b(v.w));
                *reinterpret_cast<float4*>(&Xs[cc * XSTR + q * 4]) = o;
            }
        } else {
            for (int i = t; i < 1024; i += 256) {
                int cc = i >> 4, q = i & 15;
                uint4 v = reinterpret_cast<const uint4*>(Xb + (long)(c0 + cc) * P + p0)[q];
                const __half2* hp = reinterpret_cast<const __half2*>(&v);
                float f[8];
#pragma unroll
                for (int j = 0; j < 4; j++) {
                    float2 ff = __half22float2(hp[j]);
                    f[2 * j] = ff.x; f[2 * j + 1] = ff.y;
                }
                float4 o0, o1;
                o0.x = __uint_as_float(tf32b(f[0])); o0.y = __uint_as_float(tf32b(f[1]));
                o0.z = __uint_as_float(tf32b(f[2])); o0.w = __uint_as_float(tf32b(f[3]));
                o1.x = __uint_as_float(tf32b(f[4])); o1.y = __uint_as_float(tf32b(f[5]));
                o1.z = __uint_as_float(tf32b(f[6])); o1.w = __uint_as_float(tf32b(f[7]));
                *reinterpret_cast<float4*>(&Xs[cc * XSTR + q * 8])     = o0;
                *reinterpret_cast<float4*>(&Xs[cc * XSTR + q * 8 + 4]) = o1;
            }
        }
    };

    if (C == 64) {
        loadX(0);
        __syncthreads();

        int nT = OCpad >> 6;
        YT* Yb = Y + (long)b * ybs;
        for (int ocT = 0; ocT < nT; ocT++) {
            int oc0 = ocT * 64;
            for (int i = t; i < 4096; i += 256) {
                int cc = i >> 6, oo = i & 63;
                Ws[cc * WSTR + oo] = __uint_as_float(tf32b(Wp[(long)cc * OCpad + oc0 + oo]));
            }
            __syncthreads();

            float acc[8][4];
#pragma unroll
            for (int nt = 0; nt < 8; nt++)
#pragma unroll
                for (int j = 0; j < 4; j++) acc[nt][j] = 0.f;

#pragma unroll
            for (int kc = 0; kc < 8; kc++) {
                int kb = kc * 8 + k4;
                unsigned a0 = __float_as_uint(Xs[kb * XSTR + pw + g]);
                unsigned a1 = __float_as_uint(Xs[kb * XSTR + pw + g + 8]);
                unsigned a2 = __float_as_uint(Xs[(kb + 4) * XSTR + pw + g]);
                unsigned a3 = __float_as_uint(Xs[(kb + 4) * XSTR + pw + g + 8]);
#pragma unroll
                for (int nt = 0; nt < 8; nt++) {
                    unsigned b0 = __float_as_uint(Ws[kb * WSTR + nt * 8 + g]);
                    unsigned b1 = __float_as_uint(Ws[(kb + 4) * WSTR + nt * 8 + g]);
                    mma8(acc[nt], a0, a1, a2, a3, b0, b1);
                }
            }

#pragma unroll
            for (int nt = 0; nt < 8; nt++) {
                int oc = oc0 + nt * 8 + k4 * 2;
                int px = p0 + pw + g;
                if (oc < OC) {
                    float bb = bias[oc];
                    float v0 = acc[nt][0] + bb, v2 = acc[nt][2] + bb;
                    if (relu) { v0 = fmaxf(v0, 0.f); v2 = fmaxf(v2, 0.f); }
                    Yb[(long)oc * P + px]     = (YT)v0;
                    Yb[(long)oc * P + px + 8] = (YT)v2;
                }
                if (oc + 1 < OC) {
                    float bb = bias[oc + 1];
                    float v1 = acc[nt][1] + bb, v3 = acc[nt][3] + bb;
                    if (relu) { v1 = fmaxf(v1, 0.f); v3 = fmaxf(v3, 0.f); }
                    Yb[(long)(oc + 1) * P + px]     = (YT)v1;
                    Yb[(long)(oc + 1) * P + px + 8] = (YT)v3;
                }
            }
            __syncthreads();
        }
    } else {
        float acc[8][4];
#pragma unroll
        for (int nt = 0; nt < 8; nt++)
#pragma unroll
            for (int j = 0; j < 4; j++) acc[nt][j] = 0.f;

        for (int c0 = 0; c0 < C; c0 += 64) {
            loadX(c0);
            for (int i = t; i < 4096; i += 256) {
                int cc = i >> 6, oo = i & 63;
                Ws[cc * WSTR + oo] = __uint_as_float(tf32b(Wp[(long)(c0 + cc) * OCpad + oo]));
            }
            __syncthreads();

#pragma unroll
            for (int kc = 0; kc < 8; kc++) {
                int kb = kc * 8 + k4;
                unsigned a0 = __float_as_uint(Xs[kb * XSTR + pw + g]);
                unsigned a1 = __float_as_uint(Xs[kb * XSTR + pw + g + 8]);
                unsigned a2 = __float_as_uint(Xs[(kb + 4) * XSTR + pw + g]);
                unsigned a3 = __float_as_uint(Xs[(kb + 4) * XSTR + pw + g + 8]);
#pragma unroll
                for (int nt = 0; nt < 8; nt++) {
                    unsigned b0 = __float_as_uint(Ws[kb * WSTR + nt * 8 + g]);
                    unsigned b1 = __float_as_uint(Ws[(kb + 4) * WSTR + nt * 8 + g]);
                    mma8(acc[nt], a0, a1, a2, a3, b0, b1);
                }
            }
            __syncthreads();
        }

        if (msum == nullptr) {
            YT* Yb = Y + (long)b * ybs;
#pragma unroll
            for (int nt = 0; nt < 8; nt++) {
                int oc = nt * 8 + k4 * 2;
                int px = p0 + pw + g;
                float b0v = bias[oc], b1v = bias[oc + 1];
                float v0 = acc[nt][0] + b0v, v1 = acc[nt][1] + b1v;
                float v2 = acc[nt][2] + b0v, v3 = acc[nt][3] + b1v;
                if (relu) {
                    v0 = fmaxf(v0, 0.f); v1 = fmaxf(v1, 0.f);
                    v2 = fmaxf(v2, 0.f); v3 = fmaxf(v3, 0.f);
                }
                Yb[(long)oc * P + px]           = (YT)v0;
                Yb[(long)(oc + 1) * P + px]     = (YT)v1;
                Yb[(long)oc * P + px + 8]       = (YT)v2;
                Yb[(long)(oc + 1) * P + px + 8] = (YT)v3;
            }
        } else {
#pragma unroll
            for (int nt = 0; nt < 8; nt++) {
                int oc = nt * 8 + k4 * 2;
                float b0v = bias[oc], b1v = bias[oc + 1];
                float s0 = fmaxf(acc[nt][0] + b0v, 0.f) + fmaxf(acc[nt][2] + b0v, 0.f);
                float s1 = fmaxf(acc[nt][1] + b1v, 0.f) + fmaxf(acc[nt][3] + b1v, 0.f);
#pragma unroll
                for (int off = 4; off < 32; off <<= 1) {
                    s0 += __shfl_xor_sync(0xffffffff, s0, off);
                    s1 += __shfl_xor_sync(0xffffffff, s1, off);
                }
                if (lane < 4) {
                    red[wid * 64 + oc]     = s0;
                    red[wid * 64 + oc + 1] = s1;
                }
            }
            __syncthreads();
            if (t < 64) {
                float s = 0.f;
#pragma unroll
                for (int w = 0; w < 8; w++) s += red[w * 64 + t];
                msum[((long)b * 64 + t) * gridDim.x + blockIdx.x] = s;
            }
        }
    }
}

// ---------------- finish mean ----------------
__global__ void mean_finish_kernel(const float* __restrict__ msum, float* __restrict__ att)
{
    int o = blockIdx.x, b = blockIdx.y;
    const float* p = msum + ((long)b * 64 + o) * PTILES;
    float s = 0.f;
    for (int i = threadIdx.x; i < PTILES; i += 32) s += p[i];
#pragma unroll
    for (int off = 16; off > 0; off >>= 1) s += __shfl_xor_sync(0xffffffff, s, off);
    if (threadIdx.x == 0) att[b * 64 + o] = s / (float)PP;
}

// ---------------- bilinear sample (interior fast path) ----------------
__device__ __forceinline__ float msample(const float* __restrict__ xc, float py, float px)
{
    float fy0 = floorf(py), fx0 = floorf(px);
    float wy = py - fy0, wx = px - fx0;
    int iy0 = (int)fy0, ix0 = (int)fx0;

    if (iy0 >= 0 && iy0 < HH - 1 && ix0 >= 0 && ix0 < WW - 1) {
        const float* bptr = xc + iy0 * WW + ix0;
        float v00 = bptr[0], v01 = bptr[1];
        float v10 = bptr[WW], v11 = bptr[WW + 1];
        float a = v00 + wy * (v10 - v00);
        float c = v01 + wy * (v11 - v01);
        return a + wx * (c - a);
    }
    // border path (rare)
    int iy1 = iy0 + 1, ix1 = ix0 + 1;
    bool vy0 = (iy0 >= 0) & (iy0 < HH);
    bool vy1 = (iy1 >= 0) & (iy1 < HH);
    bool vx0 = (ix0 >= 0) & (ix0 < WW);
    bool vx1 = (ix1 >= 0) & (ix1 < WW);
    int cy0 = min(max(iy0, 0), HH - 1);
    int cy1 = min(max(iy1, 0), HH - 1);
    int cx0 = min(max(ix0, 0), WW - 1);
    int cx1 = min(max(ix1, 0), WW - 1);
    float v00 = (vy0 & vx0) ? xc[cy0 * WW + cx0] : 0.f;
    float v01 = (vy0 & vx1) ? xc[cy0 * WW + cx1] : 0.f;
    float v10 = (vy1 & vx0) ? xc[cy1 * WW + cx0] : 0.f;
    float v11 = (vy1 & vx1) ? xc[cy1 * WW + cx1] : 0.f;
    float a = v00 + wy * (v10 - v00);
    float c = v01 + wy * (v11 - v01);
    return a + wx * (c - a);
}

// ---------------- mdcn as tf32 GEMM with on-the-fly sample generation ----------------
// CHUNK = ck-rows per MMA stage (8 for k=1, else 64).
template <int KK>
__global__ void mdcn_tf32_kernel(const float* __restrict__ xin,
                                 const __half* __restrict__ om,
                                 const float* __restrict__ Wdt,
                                 const float* __restrict__ bias,
                                 __half* __restrict__ out,
                                 int branch)
{
    constexpr int K  = KK * KK;
    constexpr int CK = INC * K;
    constexpr int CHUNK = (CK <= 8) ? 8 : 64;
    constexpr int CKpad = ((CK + CHUNK - 1) / CHUNK) * CHUNK;
    constexpr int pad = KK / 2;

    extern __shared__ float smem[];
    float* Xs = smem;                  // [CHUNK][XSTR] sample tile (tf32)
    float* Ws = smem + 64 * XSTR;      // [CHUNK][WSTR]

    int b = blockIdx.z;
    int p0 = blockIdx.x * 128;
    int t = threadIdx.x;
    int lane = t & 31, wid = t >> 5;
    int pw = wid * 16;
    int g = lane >> 2, k4 = lane & 3;

    const __half* omb = om + (long)b * (3 * CK) * PP;
    const float* xb  = xin + (long)b * INC * PP;

    // per-thread fixed pixel for generation
    const int pxl = t & 127;
    const int ccb = t >> 7;            // 0 or 1
    const int p   = p0 + pxl;
    const int h   = p / WW;
    const int wxp = p - h * WW;
    const float fy = (float)(h - pad);
    const float fx = (float)(wxp - pad);

    float acc[8][4];
#pragma unroll
    for (int nt = 0; nt < 8; nt++)
#pragma unroll
        for (int j = 0; j < 4; j++) acc[nt][j] = 0.f;

    for (int c0 = 0; c0 < CKpad; c0 += CHUNK) {
        // generate CHUNK x 128 sample tile; each thread: fixed pxl, ck rows ccb, ccb+2, ...
        for (int cc = ccb; cc < CHUNK; cc += 2) {
            int ck = c0 + cc;
            float val = 0.f;
            if (ck < CK) {
                float oy = __half2float(omb[(long)(2 * ck) * PP + p]);
                float ox = __half2float(omb[(long)(2 * ck + 1) * PP + p]);
                float mr = __half2float(omb[(long)(2 * CK + ck) * PP + p]);
                float m = 1.f / (1.f + __expf(-mr));
                int c  = ck / K;
                int kk = ck - c * K;
                int ky = kk / KK;
                int kx = kk - ky * KK;
                float py = oy + (float)ky + fy;
                float px = ox + (float)kx + fx;
                val = msample(xb + c * PP, py, px) * m;
            }
            Xs[cc * XSTR + pxl] = __uint_as_float(tf32b(val));
        }
        // weights chunk (already transposed + zero padded)
        for (int i = t; i < CHUNK * 64; i += 256) {
            int cc = i >> 6, oo = i & 63;
            Ws[cc * WSTR + oo] = __uint_as_float(tf32b(Wdt[(long)(c0 + cc) * 64 + oo]));
        }
        __syncthreads();

#pragma unroll
        for (int kc = 0; kc < CHUNK / 8; kc++) {
            int kb = kc * 8 + k4;
            unsigned a0 = __float_as_uint(Xs[kb * XSTR + pw + g]);
            unsigned a1 = __float_as_uint(Xs[kb * XSTR + pw + g + 8]);
            unsigned a2 = __float_as_uint(Xs[(kb + 4) * XSTR + pw + g]);
            unsigned a3 = __float_as_uint(Xs[(kb + 4) * XSTR + pw + g + 8]);
#pragma unroll
            for (int nt = 0; nt < 8; nt++) {
                unsigned b0 = __float_as_uint(Ws[kb * WSTR + nt * 8 + g]);
                unsigned b1 = __float_as_uint(Ws[(kb + 4) * WSTR + nt * 8 + g]);
                mma8(acc[nt], a0, a1, a2, a3, b0, b1);
            }
        }
        __syncthreads();
    }

    __half* ob = out + ((long)(b * 3 + branch) * 64) * PP;
#pragma unroll
    for (int nt = 0; nt < 8; nt++) {
        int oc = nt * 8 + k4 * 2;
        int px = p0 + pw + g;
        float b0v = bias[oc], b1v = bias[oc + 1];
        float v0 = fmaxf(acc[nt][0] + b0v, 0.f);
        float v1 = fmaxf(acc[nt][1] + b1v, 0.f);
        float v2 = fmaxf(acc[nt][2] + b0v, 0.f);
        float v3 = fmaxf(acc[nt][3] + b1v, 0.f);
        ob[(long)oc * PP + px]           = (__half)v0;
        ob[(long)(oc + 1) * PP + px]     = (__half)v1;
        ob[(long)oc * PP + px + 8]       = (__half)v2;
        ob[(long)(oc + 1) * PP + px + 8] = (__half)v3;
    }
}

// ---------------- tiny head ----------------
__global__ void head_kernel(const float* __restrict__ att,
                            const float* __restrict__ fc_w, const float* __restrict__ fc_b,
                            const float* __restrict__ fw0, const float* __restrict__ fb0,
                            const float* __restrict__ fw1, const float* __restrict__ fb1,
                            const float* __restrict__ fw2, const float* __restrict__ fb2,
                            const float* __restrict__ conv_w,
                            float* __restrict__ Wbt, float* __restrict__ atts)
{
    __shared__ float a2[BN][32];
    int t = threadIdx.x;
    if (t < BN * 32) {
        int b = t >> 5, o = t & 31;
        float s = fc_b[o];
        for (int c = 0; c < 64; c++) s += fc_w[o * 64 + c] * att[b * 64 + c];
        a2[b][o] = fmaxf(s, 0.f);
    }
    __syncthreads();
    __shared__ float as[BN][192];
    for (int idx = t; idx < BN * 192; idx += blockDim.x) {
        int b = idx / 192, r = idx % 192;
        int i = r / 64, o = r % 64;
        const float* fw = (i == 0) ? fw0 : ((i == 1) ? fw1 : fw2);
        const float* fb = (i == 0) ? fb0 : ((i == 1) ? fb1 : fb2);
        float s = fb[o];
        for (int c = 0; c < 32; c++) s += fw[o * 32 + c] * a2[b][c];
        as[b][r] = s;
        atts[idx] = s;
    }
    __syncthreads();
    for (int idx = t; idx < BN * 192 * 64; idx += blockDim.x) {
        int b  = idx / (192 * 64);
        int r  = idx % (192 * 64);
        int tc = r / 64;
        int o  = r % 64;
        Wbt[idx] = conv_w[o * 192 + tc] * as[b][tc];
    }
}

// ---------------- launch ----------------
extern "C" void kernel_launch(void* const* d_in, const int* in_sizes, int n_in,
                              void* d_out, int out_size)
{
    (void)in_sizes; (void)n_in; (void)out_size;
    const float* fea    = (const float*)d_in[0];
    const float* inputs = (const float*)d_in[1];
    const float* attn_w = (const float*)d_in[20];
    const float* attn_b = (const float*)d_in[21];
    const float* fc_w   = (const float*)d_in[22];
    const float* fc_b   = (const float*)d_in[23];
    const float* conv_w = (const float*)d_in[30];
    const float* conv_b = (const float*)d_in[31];

    float *dw, *attp, *att, *atts, *Wt, *Wdt, *Wbt, *eb;
    __half *om, *stack;
    cudaGetSymbolAddress((void**)&dw, g_dw);
    cudaGetSymbolAddress((void**)&om, g_om);
    cudaGetSymbolAddress((void**)&stack, g_stack);
    cudaGetSymbolAddress((void**)&attp, g_attp);
    cudaGetSymbolAddress((void**)&att, g_att);
    cudaGetSymbolAddress((void**)&atts, g_atts);
    cudaGetSymbolAddress((void**)&Wt, g_Wt);
    cudaGetSymbolAddress((void**)&Wdt, g_Wdt);
    cudaGetSymbolAddress((void**)&Wbt, g_Wbt);
    cudaGetSymbolAddress((void**)&eb, g_eb);

    cudaFuncSetAttribute(pw_gemm_tf32_kernel<float, __half>,
                         cudaFuncAttributeMaxDynamicSharedMemorySize, GEMM_SMEM);
    cudaFuncSetAttribute(pw_gemm_tf32_kernel<__half, float>,
                         cudaFuncAttributeMaxDynamicSharedMemorySize, GEMM_SMEM);
    cudaFuncSetAttribute(mdcn_tf32_kernel<1>,
                         cudaFuncAttributeMaxDynamicSharedMemorySize, GEMM_SMEM);
    cudaFuncSetAttribute(mdcn_tf32_kernel<3>,
                         cudaFuncAttributeMaxDynamicSharedMemorySize, GEMM_SMEM);
    cudaFuncSetAttribute(mdcn_tf32_kernel<5>,
                         cudaFuncAttributeMaxDynamicSharedMemorySize, GEMM_SMEM);

    const int wtOff[3]  = {WT_B0, WT_B1, WT_B2};
    const int wdOff[3]  = {WD_B0, WD_B1, WD_B2};
    const int ocPad[3]  = {64, 192, 576};
    const int ckPad[3]  = {8, 64, 192};
    const int ckArr[3]  = {7, 63, 175};

    // weight transposes (tiny)
    transposeW_scaled_kernel<<<(64 * 64 + 255) / 256, 256>>>(
        (const float*)d_in[4], (const float*)d_in[2], (const float*)d_in[3],
        (const float*)d_in[5], Wt + WT_B0, eb, 21, 64, 64);
    for (int i = 1; i < 3; i++) {
        const float* pww = (const float*)d_in[4 + 6 * i];
        int k = 2 * i + 1;
        int oc = INC * 3 * k * k;
        int n = 64 * ocPad[i];
        transposeW_kernel<<<(n + 255) / 256, 256>>>(pww, Wt + wtOff[i], oc, ocPad[i], 64);
    }
    transposeW_kernel<<<(192 * 64 + 255) / 256, 256>>>(attn_w, Wt + WT_ATT, 64, 64, 192);
    for (int i = 0; i < 3; i++) {
        const float* dcnw = (const float*)d_in[6 + 6 * i];
        int n = ckPad[i] * 64;
        transposeWdcn_kernel<<<(n + 255) / 256, 256>>>(dcnw, Wdt + wdOff[i], ckArr[i], ckPad[i]);
    }

    for (int i = 0; i < 3; i++) {
        const float* dww  = (const float*)d_in[2 + 6 * i];
        const float* dwb  = (const float*)d_in[3 + 6 * i];
        const float* pwb  = (const float*)d_in[5 + 6 * i];
        const float* dcnb = (const float*)d_in[7 + 6 * i];
        int k  = 2 * i + 1;
        int oc = INC * 3 * k * k;   // 21, 189, 525

        const float* gx = dw;
        const float* gb = pwb;
        if (i == 0) { gx = fea; gb = eb; }
        else {
            int total4 = BN * CF * PP / 4;
            int blocks = (total4 + 255) / 256;
            if (i == 1) dw_conv_kernel<3><<<blocks, 256>>>(fea, dww, dwb, dw);
            else        dw_conv_kernel<5><<<blocks, 256>>>(fea, dww, dwb, dw);
        }

        dim3 ggrid(PTILES, 1, BN);
        pw_gemm_tf32_kernel<float, __half><<<ggrid, 256, GEMM_SMEM>>>(
            gx, Wt + wtOff[i], gb, om,
            64, oc, ocPad[i],
            (long)64 * PP, (long)oc * PP, 0, 0, nullptr);

        dim3 mgrid(PTILES, 1, BN);
        if (i == 0) mdcn_tf32_kernel<1><<<mgrid, 256, GEMM_SMEM>>>(inputs, om, Wdt + wdOff[i], dcnb, stack, i);
        if (i == 1) mdcn_tf32_kernel<3><<<mgrid, 256, GEMM_SMEM>>>(inputs, om, Wdt + wdOff[i], dcnb, stack, i);
        if (i == 2) mdcn_tf32_kernel<5><<<mgrid, 256, GEMM_SMEM>>>(inputs, om, Wdt + wdOff[i], dcnb, stack, i);
    }

    // attention: relu(pw(stack, attn_w)) -> mean (fused partial sums)
    dim3 agrid(PTILES, 1, BN);
    pw_gemm_tf32_kernel<__half, float><<<agrid, 256, GEMM_SMEM>>>(
        stack, Wt + WT_ATT, attn_b, nullptr,
        192, 64, 64,
        (long)192 * PP, 0, 0, 1, attp);
    dim3 rgrid(64, BN);
    mean_finish_kernel<<<rgrid, 32>>>(attp, att);

    head_kernel<<<1, 256>>>(att, fc_w, fc_b,
                            (const float*)d_in[24], (const float*)d_in[25],
                            (const float*)d_in[26], (const float*)d_in[27],
                            (const float*)d_in[28], (const float*)d_in[29],
                            conv_w, Wbt, atts);

    // final: relu(pw(stack, Wbt)) with atts folded into per-batch transposed weights
    pw_gemm_tf32_kernel<__half, float><<<agrid, 256, GEMM_SMEM>>>(
        stack, Wbt, conv_b, (float*)d_out,
        192, 64, 64,
        (long)192 * PP, (long)64 * PP, (long)192 * 64, 1, nullptr);
}